// round 8
// baseline (speedup 1.0000x reference)
#include <cuda_runtime.h>
#include <math.h>

#define Bdim 128
#define Ldim 256
#define Hdim 512
#define H3   1536
#define OUTD 256
#define BL   (Bdim*Ldim)   // 32768
#define NBLK 128

// ---------------- scratch (device globals) ----------------------------------
__device__ float g_xmean[Bdim*Hdim];
__device__ float g_delta[BL*Hdim];
__device__ float g_xhat [BL*Hdim];
__device__ float g_gammah[BL*Hdim];
__device__ float g_pre  [BL*H3];
__device__ float g_hseq [BL*Hdim];
__device__ float g_h    [Bdim*Hdim];
__device__ float g_z    [Bdim*Hdim];
__device__ float g_rh   [Bdim*Hdim];
__device__ unsigned g_arrA[4][128];      // sub-counters at [rg][sub*32]
__device__ unsigned g_arrM[4*32];        // master counter per group
__device__ volatile unsigned g_relS[4*32];

// ---------------- two-level tree barrier (32 blocks: 4 subs of 8) -----------
__device__ __forceinline__ void groupbar(int rg, int tn) {
    __syncthreads();
    if (threadIdx.x == 0) {
        __threadfence();
        unsigned gen = g_relS[rg * 32];
        bool released = false;
        int sub = tn >> 3;
        if (atomicInc(&g_arrA[rg][sub * 32], 7u) == 7u) {
            if (atomicInc(&g_arrM[rg * 32], 3u) == 3u) {
                __threadfence();
                g_relS[rg * 32] = gen + 1u;
                released = true;
            }
        }
        if (!released)
            while (g_relS[rg * 32] == gen) { __nanosleep(20); }
    }
    __syncthreads();
}

__device__ __forceinline__ float sigmoidf_(float x) { return 1.f / (1.f + expf(-x)); }

__device__ __forceinline__ unsigned f2tf32(float f) {
    unsigned r; asm("cvt.rna.tf32.f32 %0, %1;" : "=r"(r) : "f"(f)); return r;
}
__device__ __forceinline__ void mma_tf32(float* c, const unsigned* a, const unsigned* b) {
    asm volatile("mma.sync.aligned.m16n8k8.row.col.f32.tf32.tf32.f32 "
        "{%0,%1,%2,%3}, {%4,%5,%6,%7}, {%8,%9}, {%0,%1,%2,%3};"
        : "+f"(c[0]), "+f"(c[1]), "+f"(c[2]), "+f"(c[3])
        : "r"(a[0]), "r"(a[1]), "r"(a[2]), "r"(a[3]), "r"(b[0]), "r"(b[1]));
}

// ---------------- K1: x_mean -------------------------------------------------
__global__ void __launch_bounds__(256) k_xmean(const float* __restrict__ C,
                                               const int* __restrict__ mask) {
    int idx = blockIdx.x * 256 + threadIdx.x;
    int b = idx >> 9, h = idx & 511;
    const int* mp = mask + (size_t)b * Ldim * Hdim + h;
    float s = 0.f, cnt = 0.f;
    #pragma unroll 4
    for (int l = 0; l < Ldim; l++) {
        float m = (float)mp[l * Hdim];
        s   += m * C[l * Hdim + h];
        cnt += m;
    }
    g_xmean[idx] = s / fmaxf(cnt, 1.f);
}

// ---------------- K2: elementwise scans --------------------------------------
__global__ void __launch_bounds__(256) k_scan(const float* __restrict__ C,
                                              const float* __restrict__ t,
                                              const int* __restrict__ mask,
                                              const float* __restrict__ w_gx,
                                              const float* __restrict__ b_gx) {
    int idx = blockIdx.x * 256 + threadIdx.x;
    int b = idx >> 9, h = idx & 511;
    float xm = g_xmean[idx];
    float xl = xm, dprev = 0.f, mprev = 1.f, tprev = 0.f;
    float wg = w_gx[h], bg = b_gx[h];
    const int* mp = mask + (size_t)b * Ldim * Hdim + h;
    const float* tp = t + b * Ldim;
    for (int l = 0; l < Ldim; l++) {
        float tc = tp[l];
        float dt = (l == 0) ? 0.f : (tc - tprev);
        tprev = tc;
        float m = (float)mp[l * Hdim];
        float delta = dt + (1.f - mprev) * dprev;
        float gx = expf(-fmaxf(0.f, wg * delta + bg));
        float x  = C[(l << 9) + h];
        int gi = ((b * Ldim + l) << 9) + h;
        g_delta[gi] = delta;
        g_xhat[gi]  = m * x + (1.f - m) * (gx * xl + (1.f - gx) * xm);
        xl = m * x + (1.f - m) * xl;
        dprev = delta; mprev = m;
    }
}

// =============================================================================
// tf32 mma GEMMs — fragment-major A smem layout (LDS.128 fragment loads).
// =============================================================================
#define BSTR 136
#define AFRB 288
#define AFRW 2304

#define STORE_AFRAG(Abuf, base, v)                                  \
    do {                                                            \
        (Abuf)[(base) + 0]  = f2tf32((v).x);                        \
        (Abuf)[(base) + 8]  = f2tf32((v).y);                        \
        (Abuf)[(base) + 16] = f2tf32((v).z);                        \
        (Abuf)[(base) + 24] = f2tf32((v).w);                        \
    } while (0)

__global__ void __launch_bounds__(256, 2) k_gh_mma(const float* __restrict__ Bw,
                                                   const float* __restrict__ bias) {
    __shared__ __align__(16) unsigned Afr[2][AFRW];
    __shared__ unsigned Bs[2][16 * BSTR];
    const int tid = threadIdx.x;
    const int bn = blockIdx.x * 128, bm = blockIdx.y * 128;
    const int wid = tid >> 5, lane = tid & 31;
    const int wm = (wid >> 2) * 64, wn = (wid & 3) * 32;
    const int g = lane >> 2, tg = lane & 3;
    const int arow = tid >> 2, ac4 = (tid & 3) * 4;
    const int brow = tid >> 5, bc4 = lane * 4;
    const int abase0 = (arow >> 4) * AFRB + (arow & 7) * 36 + (ac4 >> 3) * 4
                     + ((arow >> 3) & 1) + ((ac4 >> 2) & 1) * 2;
    const int abase1 = abase0 + 4 * AFRB;
    const int mbkw = (wid >> 2) * 4;

    float acc[4][4][4];
    #pragma unroll
    for (int i = 0; i < 4; i++)
        #pragma unroll
        for (int j = 0; j < 4; j++)
            #pragma unroll
            for (int q = 0; q < 4; q++) acc[i][j][q] = 0.f;

    float4 av0, av1, bv0, bv1;
    av0 = *(const float4*)&g_delta[(size_t)(bm + arow) * Hdim + ac4];
    av1 = *(const float4*)&g_delta[(size_t)(bm + arow + 64) * Hdim + ac4];
    bv0 = *(const float4*)&Bw[(size_t)(brow) * Hdim + bn + bc4];
    bv1 = *(const float4*)&Bw[(size_t)(brow + 8) * Hdim + bn + bc4];
    {
        unsigned* A = Afr[0]; unsigned* B = Bs[0];
        STORE_AFRAG(A, abase0, av0);
        STORE_AFRAG(A, abase1, av1);
        B[brow * BSTR + bc4 + 0] = f2tf32(bv0.x); B[brow * BSTR + bc4 + 1] = f2tf32(bv0.y);
        B[brow * BSTR + bc4 + 2] = f2tf32(bv0.z); B[brow * BSTR + bc4 + 3] = f2tf32(bv0.w);
        B[(brow + 8) * BSTR + bc4 + 0] = f2tf32(bv1.x); B[(brow + 8) * BSTR + bc4 + 1] = f2tf32(bv1.y);
        B[(brow + 8) * BSTR + bc4 + 2] = f2tf32(bv1.z); B[(brow + 8) * BSTR + bc4 + 3] = f2tf32(bv1.w);
    }
    __syncthreads();

    const int KT = Hdim / 16;
    for (int kt = 0; kt < KT; kt++) {
        if (kt + 1 < KT) {
            int k0 = (kt + 1) * 16;
            av0 = *(const float4*)&g_delta[(size_t)(bm + arow) * Hdim + k0 + ac4];
            av1 = *(const float4*)&g_delta[(size_t)(bm + arow + 64) * Hdim + k0 + ac4];
            bv0 = *(const float4*)&Bw[(size_t)(k0 + brow) * Hdim + bn + bc4];
            bv1 = *(const float4*)&Bw[(size_t)(k0 + brow + 8) * Hdim + bn + bc4];
        }
        const unsigned* A = Afr[kt & 1];
        const unsigned* B = Bs[kt & 1];
        #pragma unroll
        for (int ks = 0; ks < 2; ks++) {
            unsigned af[4][4], bf[4][2];
            #pragma unroll
            for (int mt = 0; mt < 4; mt++) {
                uint4 fa = *(const uint4*)&A[(mbkw + mt) * AFRB + g * 36 + tg * 8 + ks * 4];
                af[mt][0] = fa.x; af[mt][1] = fa.y; af[mt][2] = fa.z; af[mt][3] = fa.w;
            }
            #pragma unroll
            for (int nt = 0; nt < 4; nt++) {
                int nb = wn + nt * 8;
                bf[nt][0] = B[(ks * 8 + tg) * BSTR + nb + g];
                bf[nt][1] = B[(ks * 8 + tg + 4) * BSTR + nb + g];
            }
            #pragma unroll
            for (int mt = 0; mt < 4; mt++)
                #pragma unroll
                for (int nt = 0; nt < 4; nt++)
                    mma_tf32(acc[mt][nt], af[mt], bf[nt]);
        }
        if (kt + 1 < KT) {
            unsigned* An = Afr[(kt + 1) & 1]; unsigned* Bn = Bs[(kt + 1) & 1];
            STORE_AFRAG(An, abase0, av0);
            STORE_AFRAG(An, abase1, av1);
            Bn[brow * BSTR + bc4 + 0] = f2tf32(bv0.x); Bn[brow * BSTR + bc4 + 1] = f2tf32(bv0.y);
            Bn[brow * BSTR + bc4 + 2] = f2tf32(bv0.z); Bn[brow * BSTR + bc4 + 3] = f2tf32(bv0.w);
            Bn[(brow + 8) * BSTR + bc4 + 0] = f2tf32(bv1.x); Bn[(brow + 8) * BSTR + bc4 + 1] = f2tf32(bv1.y);
            Bn[(brow + 8) * BSTR + bc4 + 2] = f2tf32(bv1.z); Bn[(brow + 8) * BSTR + bc4 + 3] = f2tf32(bv1.w);
        }
        __syncthreads();
    }

    #pragma unroll
    for (int mt = 0; mt < 4; mt++) {
        #pragma unroll
        for (int nt = 0; nt < 4; nt++) {
            int col = bn + wn + nt * 8 + tg * 2;
            float b0 = bias[col], b1 = bias[col + 1];
            int r0 = bm + wm + mt * 16 + g;
            float2 o0, o1;
            o0.x = expf(-fmaxf(0.f, acc[mt][nt][0] + b0));
            o0.y = expf(-fmaxf(0.f, acc[mt][nt][1] + b1));
            o1.x = expf(-fmaxf(0.f, acc[mt][nt][2] + b0));
            o1.y = expf(-fmaxf(0.f, acc[mt][nt][3] + b1));
            *(float2*)&g_gammah[(size_t)r0 * Hdim + col] = o0;
            *(float2*)&g_gammah[(size_t)(r0 + 8) * Hdim + col] = o1;
        }
    }
}

__global__ void __launch_bounds__(256, 2) k_pre_mma(const int* __restrict__ mask,
                                                    const float* __restrict__ Wx,
                                                    const float* __restrict__ Wm,
                                                    const float* __restrict__ bias) {
    __shared__ __align__(16) unsigned Afr[2][AFRW];
    __shared__ unsigned Bs[2][16 * BSTR];
    const int tid = threadIdx.x;
    const int bn = blockIdx.x * 128, bm = blockIdx.y * 128;
    const int wid = tid >> 5, lane = tid & 31;
    const int wm = (wid >> 2) * 64, wn = (wid & 3) * 32;
    const int g = lane >> 2, tg = lane & 3;
    const int arow = tid >> 2, ac4 = (tid & 3) * 4;
    const int brow = tid >> 5, bc4 = lane * 4;
    const int abase0 = (arow >> 4) * AFRB + (arow & 7) * 36 + (ac4 >> 3) * 4
                     + ((arow >> 3) & 1) + ((ac4 >> 2) & 1) * 2;
    const int abase1 = abase0 + 4 * AFRB;
    const int mbkw = (wid >> 2) * 4;

    float acc[4][4][4];
    #pragma unroll
    for (int i = 0; i < 4; i++)
        #pragma unroll
        for (int j = 0; j < 4; j++)
            #pragma unroll
            for (int q = 0; q < 4; q++) acc[i][j][q] = 0.f;

    float4 av0, av1, bv0, bv1;
    av0 = *(const float4*)&g_xhat[(size_t)(bm + arow) * Hdim + ac4];
    av1 = *(const float4*)&g_xhat[(size_t)(bm + arow + 64) * Hdim + ac4];
    bv0 = *(const float4*)&Wx[(size_t)(brow) * H3 + bn + bc4];
    bv1 = *(const float4*)&Wx[(size_t)(brow + 8) * H3 + bn + bc4];
    {
        unsigned* A = Afr[0]; unsigned* B = Bs[0];
        STORE_AFRAG(A, abase0, av0);
        STORE_AFRAG(A, abase1, av1);
        B[brow * BSTR + bc4 + 0] = f2tf32(bv0.x); B[brow * BSTR + bc4 + 1] = f2tf32(bv0.y);
        B[brow * BSTR + bc4 + 2] = f2tf32(bv0.z); B[brow * BSTR + bc4 + 3] = f2tf32(bv0.w);
        B[(brow + 8) * BSTR + bc4 + 0] = f2tf32(bv1.x); B[(brow + 8) * BSTR + bc4 + 1] = f2tf32(bv1.y);
        B[(brow + 8) * BSTR + bc4 + 2] = f2tf32(bv1.z); B[(brow + 8) * BSTR + bc4 + 3] = f2tf32(bv1.w);
    }
    __syncthreads();

    const int KT = 64;
    for (int kt = 0; kt < KT; kt++) {
        if (kt + 1 < KT) {
            int nkt = kt + 1;
            int k0 = (nkt & 31) * 16;
            if (nkt < 32) {
                av0 = *(const float4*)&g_xhat[(size_t)(bm + arow) * Hdim + k0 + ac4];
                av1 = *(const float4*)&g_xhat[(size_t)(bm + arow + 64) * Hdim + k0 + ac4];
                bv0 = *(const float4*)&Wx[(size_t)(k0 + brow) * H3 + bn + bc4];
                bv1 = *(const float4*)&Wx[(size_t)(k0 + brow + 8) * H3 + bn + bc4];
            } else {
                int4 m0 = *(const int4*)&mask[(size_t)(bm + arow) * Hdim + k0 + ac4];
                int4 m1 = *(const int4*)&mask[(size_t)(bm + arow + 64) * Hdim + k0 + ac4];
                av0 = make_float4((float)m0.x, (float)m0.y, (float)m0.z, (float)m0.w);
                av1 = make_float4((float)m1.x, (float)m1.y, (float)m1.z, (float)m1.w);
                bv0 = *(const float4*)&Wm[(size_t)(k0 + brow) * H3 + bn + bc4];
                bv1 = *(const float4*)&Wm[(size_t)(k0 + brow + 8) * H3 + bn + bc4];
            }
        }
        const unsigned* A = Afr[kt & 1];
        const unsigned* B = Bs[kt & 1];
        #pragma unroll
        for (int ks = 0; ks < 2; ks++) {
            unsigned af[4][4], bf[4][2];
            #pragma unroll
            for (int mt = 0; mt < 4; mt++) {
                uint4 fa = *(const uint4*)&A[(mbkw + mt) * AFRB + g * 36 + tg * 8 + ks * 4];
                af[mt][0] = fa.x; af[mt][1] = fa.y; af[mt][2] = fa.z; af[mt][3] = fa.w;
            }
            #pragma unroll
            for (int nt = 0; nt < 4; nt++) {
                int nb = wn + nt * 8;
                bf[nt][0] = B[(ks * 8 + tg) * BSTR + nb + g];
                bf[nt][1] = B[(ks * 8 + tg + 4) * BSTR + nb + g];
            }
            #pragma unroll
            for (int mt = 0; mt < 4; mt++)
                #pragma unroll
                for (int nt = 0; nt < 4; nt++)
                    mma_tf32(acc[mt][nt], af[mt], bf[nt]);
        }
        if (kt + 1 < KT) {
            unsigned* An = Afr[(kt + 1) & 1]; unsigned* Bn = Bs[(kt + 1) & 1];
            STORE_AFRAG(An, abase0, av0);
            STORE_AFRAG(An, abase1, av1);
            Bn[brow * BSTR + bc4 + 0] = f2tf32(bv0.x); Bn[brow * BSTR + bc4 + 1] = f2tf32(bv0.y);
            Bn[brow * BSTR + bc4 + 2] = f2tf32(bv0.z); Bn[brow * BSTR + bc4 + 3] = f2tf32(bv0.w);
            Bn[(brow + 8) * BSTR + bc4 + 0] = f2tf32(bv1.x); Bn[(brow + 8) * BSTR + bc4 + 1] = f2tf32(bv1.y);
            Bn[(brow + 8) * BSTR + bc4 + 2] = f2tf32(bv1.z); Bn[(brow + 8) * BSTR + bc4 + 3] = f2tf32(bv1.w);
        }
        __syncthreads();
    }

    #pragma unroll
    for (int mt = 0; mt < 4; mt++) {
        #pragma unroll
        for (int nt = 0; nt < 4; nt++) {
            int col = bn + wn + nt * 8 + tg * 2;
            float b0 = bias[col], b1 = bias[col + 1];
            int r0 = bm + wm + mt * 16 + g;
            float2 o0, o1;
            o0.x = acc[mt][nt][0] + b0; o0.y = acc[mt][nt][1] + b1;
            o1.x = acc[mt][nt][2] + b0; o1.y = acc[mt][nt][3] + b1;
            *(float2*)&g_pre[(size_t)r0 * H3 + col] = o0;
            *(float2*)&g_pre[(size_t)(r0 + 8) * H3 + col] = o1;
        }
    }
}

// ---------------- K6 (mma): out = h_seq @ W_out + b_out ----------------------
__global__ void __launch_bounds__(256, 2) k_out_mma(const float* __restrict__ Bw,
                                                    const float* __restrict__ bias,
                                                    float* __restrict__ out) {
    __shared__ __align__(16) unsigned Afr[2][AFRW];
    __shared__ unsigned Bs[2][16 * BSTR];
    const int tid = threadIdx.x;
    const int bn = blockIdx.x * 128, bm = blockIdx.y * 128;
    const int wid = tid >> 5, lane = tid & 31;
    const int wm = (wid >> 2) * 64, wn = (wid & 3) * 32;
    const int g = lane >> 2, tg = lane & 3;
    const int arow = tid >> 2, ac4 = (tid & 3) * 4;
    const int brow = tid >> 5, bc4 = lane * 4;
    const int abase0 = (arow >> 4) * AFRB + (arow & 7) * 36 + (ac4 >> 3) * 4
                     + ((arow >> 3) & 1) + ((ac4 >> 2) & 1) * 2;
    const int abase1 = abase0 + 4 * AFRB;
    const int mbkw = (wid >> 2) * 4;

    float acc[4][4][4];
    #pragma unroll
    for (int i = 0; i < 4; i++)
        #pragma unroll
        for (int j = 0; j < 4; j++)
            #pragma unroll
            for (int q = 0; q < 4; q++) acc[i][j][q] = 0.f;

    float4 av0, av1, bv0, bv1;
    av0 = *(const float4*)&g_hseq[(size_t)(bm + arow) * Hdim + ac4];
    av1 = *(const float4*)&g_hseq[(size_t)(bm + arow + 64) * Hdim + ac4];
    bv0 = *(const float4*)&Bw[(size_t)(brow) * OUTD + bn + bc4];
    bv1 = *(const float4*)&Bw[(size_t)(brow + 8) * OUTD + bn + bc4];
    {
        unsigned* A = Afr[0]; unsigned* B = Bs[0];
        STORE_AFRAG(A, abase0, av0);
        STORE_AFRAG(A, abase1, av1);
        B[brow * BSTR + bc4 + 0] = f2tf32(bv0.x); B[brow * BSTR + bc4 + 1] = f2tf32(bv0.y);
        B[brow * BSTR + bc4 + 2] = f2tf32(bv0.z); B[brow * BSTR + bc4 + 3] = f2tf32(bv0.w);
        B[(brow + 8) * BSTR + bc4 + 0] = f2tf32(bv1.x); B[(brow + 8) * BSTR + bc4 + 1] = f2tf32(bv1.y);
        B[(brow + 8) * BSTR + bc4 + 2] = f2tf32(bv1.z); B[(brow + 8) * BSTR + bc4 + 3] = f2tf32(bv1.w);
    }
    __syncthreads();

    const int KT = Hdim / 16;
    for (int kt = 0; kt < KT; kt++) {
        if (kt + 1 < KT) {
            int k0 = (kt + 1) * 16;
            av0 = *(const float4*)&g_hseq[(size_t)(bm + arow) * Hdim + k0 + ac4];
            av1 = *(const float4*)&g_hseq[(size_t)(bm + arow + 64) * Hdim + k0 + ac4];
            bv0 = *(const float4*)&Bw[(size_t)(k0 + brow) * OUTD + bn + bc4];
            bv1 = *(const float4*)&Bw[(size_t)(k0 + brow + 8) * OUTD + bn + bc4];
        }
        const unsigned* A = Afr[kt & 1];
        const unsigned* B = Bs[kt & 1];
        #pragma unroll
        for (int ks = 0; ks < 2; ks++) {
            unsigned af[4][4], bf[4][2];
            #pragma unroll
            for (int mt = 0; mt < 4; mt++) {
                uint4 fa = *(const uint4*)&A[(mbkw + mt) * AFRB + g * 36 + tg * 8 + ks * 4];
                af[mt][0] = fa.x; af[mt][1] = fa.y; af[mt][2] = fa.z; af[mt][3] = fa.w;
            }
            #pragma unroll
            for (int nt = 0; nt < 4; nt++) {
                int nb = wn + nt * 8;
                bf[nt][0] = B[(ks * 8 + tg) * BSTR + nb + g];
                bf[nt][1] = B[(ks * 8 + tg + 4) * BSTR + nb + g];
            }
            #pragma unroll
            for (int mt = 0; mt < 4; mt++)
                #pragma unroll
                for (int nt = 0; nt < 4; nt++)
                    mma_tf32(acc[mt][nt], af[mt], bf[nt]);
        }
        if (kt + 1 < KT) {
            unsigned* An = Afr[(kt + 1) & 1]; unsigned* Bn = Bs[(kt + 1) & 1];
            STORE_AFRAG(An, abase0, av0);
            STORE_AFRAG(An, abase1, av1);
            Bn[brow * BSTR + bc4 + 0] = f2tf32(bv0.x); Bn[brow * BSTR + bc4 + 1] = f2tf32(bv0.y);
            Bn[brow * BSTR + bc4 + 2] = f2tf32(bv0.z); Bn[brow * BSTR + bc4 + 3] = f2tf32(bv0.w);
            Bn[(brow + 8) * BSTR + bc4 + 0] = f2tf32(bv1.x); Bn[(brow + 8) * BSTR + bc4 + 1] = f2tf32(bv1.y);
            Bn[(brow + 8) * BSTR + bc4 + 2] = f2tf32(bv1.z); Bn[(brow + 8) * BSTR + bc4 + 3] = f2tf32(bv1.w);
        }
        __syncthreads();
    }

    #pragma unroll
    for (int mt = 0; mt < 4; mt++) {
        #pragma unroll
        for (int nt = 0; nt < 4; nt++) {
            int col = bn + wn + nt * 8 + tg * 2;
            float b0 = bias[col], b1 = bias[col + 1];
            int r0 = bm + wm + mt * 16 + g;
            float2 o0, o1;
            o0.x = acc[mt][nt][0] + b0; o0.y = acc[mt][nt][1] + b1;
            o1.x = acc[mt][nt][2] + b0; o1.y = acc[mt][nt][3] + b1;
            *(float2*)&out[(size_t)r0 * OUTD + col] = o0;
            *(float2*)&out[(size_t)(r0 + 8) * OUTD + col] = o1;
        }
    }
}

// =============================================================================
// K5: persistent sequential recurrence — R7 + tree barrier + γ-preload.
// =============================================================================
#define OFF_WH1 0
#define WS1     40
#define OFF_WH3 20480
#define WS3     20
#define OFF_AB  30720
#define AS      516
#define OFF_RED 47232
#define RSTR1   36
#define RKG1    (32*RSTR1)
#define RSTR2   20
#define RKG2    (32*RSTR2)
#define SMEM_SEQ ((OFF_RED + 8*RKG1) * 4)   // 225792 B

__global__ void __launch_bounds__(256, 1) k_seq(const float* __restrict__ Wh) {
    extern __shared__ unsigned smu[];
    unsigned* Wh1t = smu + OFF_WH1;
    unsigned* Wh3t = smu + OFF_WH3;
    unsigned* Ab   = smu + OFF_AB;
    float*    Abf  = (float*)Ab;
    float*    Red  = (float*)(smu + OFF_RED);

    const int tid = threadIdx.x;
    const int blk = blockIdx.x;
    const int rg  = blk >> 5;
    const int tn  = blk & 31;
    const int m0  = rg * 32;
    const int n0  = tn * 32;
    const int n02 = tn * 16;

    for (int i = tid; i < 512 * 32; i += 256) {
        int k = i >> 5, n = i & 31;
        Wh1t[k * WS1 + n] = f2tf32(Wh[(size_t)k * H3 + n0 + n]);
    }
    for (int i = tid; i < 512 * 16; i += 256) {
        int k = i >> 4, n = i & 15;
        Wh3t[k * WS3 + n] = f2tf32(Wh[(size_t)k * H3 + 1024 + n02 + n]);
    }
    if (tn == 0)
        for (int i = tid; i < 32 * 512; i += 256) g_h[m0 * 512 + i] = 0.f;

    const int lane = tid & 31, kg = tid >> 5;
    const int g = lane >> 2, tg = lane & 3;
    const int kbase = kg * 64;
    const int pr = tid >> 3, pc = (tid & 7) * 4;
    const int rr1 = tid >> 3, cc1 = (tid * 4) & 31;
    const int rr2 = tid >> 3, cc2 = (tid * 2) & 15;
    const int nn1 = (n0 >= 512 ? n0 - 512 : 0) + cc1;

    // preload gamma(0) raw floats into Ab (same thread slots produce1 reads)
    {
        const float* grow = g_gammah + (size_t)((m0 + pr) * Ldim) * 512;
        #pragma unroll
        for (int j = 0; j < 16; j++) {
            int k = pc + 32 * j;
            *(float4*)&Abf[pr * AS + k] = *(const float4*)(grow + k);
        }
    }
    groupbar(rg, tn);

    for (int step = 0; step < Ldim; step++) {
        // ---------- epilogue prefetches (overlap with produce+GEMM1) ----------
        float4 pf_pre4 = __ldcg((const float4*)&g_pre[(size_t)((m0 + rr1) * Ldim + step) * H3 + n0 + cc1]);
        float2 pf_pre2 = __ldcg((const float2*)&g_pre[(size_t)((m0 + rr2) * Ldim + step) * H3 + 1024 + n02 + cc2]);
        float2 pf_gm2  = *(const float2*)&g_gammah[(size_t)((m0 + rr2) * Ldim + step) * 512 + n02 + cc2];
        float2 pf_h2   = __ldcg((const float2*)&g_h[(m0 + rr2) * 512 + n02 + cc2]);
        float4 pf_gm1  = *(const float4*)&g_gammah[(size_t)((m0 + rr1) * Ldim + step) * 512 + nn1];
        float4 pf_h1   = __ldcg((const float4*)&g_h[(m0 + rr1) * 512 + nn1]);

        // ---------- produce A = preloaded gamma ⊙ h (tf32, in-place) ----------
        {
            const float* hrow = g_h + (m0 + pr) * 512;
            #pragma unroll
            for (int j = 0; j < 16; j++) {
                int k = pc + 32 * j;
                float4 h4 = __ldcg((const float4*)(hrow + k));
                float4 g4 = *(const float4*)&Abf[pr * AS + k];
                uint4 o;
                o.x = f2tf32(h4.x * g4.x); o.y = f2tf32(h4.y * g4.y);
                o.z = f2tf32(h4.z * g4.z); o.w = f2tf32(h4.w * g4.w);
                *(uint4*)&Ab[pr * AS + k] = o;
            }
        }
        __syncthreads();
        // ---------- GEMM1 (mma): 32x32, K-slice 64 per warp ----------
        {
            float acc[2][4][4];
            #pragma unroll
            for (int mt = 0; mt < 2; mt++)
                #pragma unroll
                for (int nt = 0; nt < 4; nt++)
                    #pragma unroll
                    for (int q = 0; q < 4; q++) acc[mt][nt][q] = 0.f;
            #pragma unroll
            for (int ks = 0; ks < 8; ks++) {
                int k = kbase + ks * 8;
                unsigned af[2][4];
                #pragma unroll
                for (int mt = 0; mt < 2; mt++) {
                    int mb = mt * 16;
                    af[mt][0] = Ab[(mb + g) * AS + k + tg];
                    af[mt][1] = Ab[(mb + g + 8) * AS + k + tg];
                    af[mt][2] = Ab[(mb + g) * AS + k + tg + 4];
                    af[mt][3] = Ab[(mb + g + 8) * AS + k + tg + 4];
                }
                unsigned bf[4][2];
                #pragma unroll
                for (int nt = 0; nt < 4; nt++) {
                    bf[nt][0] = Wh1t[(k + tg) * WS1 + nt * 8 + g];
                    bf[nt][1] = Wh1t[(k + tg + 4) * WS1 + nt * 8 + g];
                }
                #pragma unroll
                for (int mt = 0; mt < 2; mt++)
                    #pragma unroll
                    for (int nt = 0; nt < 4; nt++)
                        mma_tf32(acc[mt][nt], af[mt], bf[nt]);
            }
            #pragma unroll
            for (int mt = 0; mt < 2; mt++)
                #pragma unroll
                for (int nt = 0; nt < 4; nt++) {
                    float* base = &Red[kg * RKG1 + (mt * 16 + g) * RSTR1 + nt * 8 + tg * 2];
                    *(float2*)base = make_float2(acc[mt][nt][0], acc[mt][nt][1]);
                    *(float2*)(base + 8 * RSTR1) = make_float2(acc[mt][nt][2], acc[mt][nt][3]);
                }
        }
        __syncthreads();
        // ---------- red1: reduce + sigmoid; z or rh ----------
        {
            float4 s = *(float4*)&Red[rr1 * RSTR1 + cc1];
            #pragma unroll
            for (int q = 1; q < 8; q++) {
                float4 v = *(float4*)&Red[q * RKG1 + rr1 * RSTR1 + cc1];
                s.x += v.x; s.y += v.y; s.z += v.z; s.w += v.w;
            }
            int b = m0 + rr1;
            float s0 = sigmoidf_(s.x + pf_pre4.x);
            float s1 = sigmoidf_(s.y + pf_pre4.y);
            float s2 = sigmoidf_(s.z + pf_pre4.z);
            float s3 = sigmoidf_(s.w + pf_pre4.w);
            if (n0 < 512) {
                *(float4*)&g_z[b * 512 + n0 + cc1] = make_float4(s0, s1, s2, s3);
            } else {
                *(float4*)&g_rh[b * 512 + nn1] = make_float4(
                    s0 * pf_gm1.x * pf_h1.x, s1 * pf_gm1.y * pf_h1.y,
                    s2 * pf_gm1.z * pf_h1.z, s3 * pf_gm1.w * pf_h1.w);
            }
        }
        groupbar(rg, tn);

        // ---------- post-barrier prefetch: z ----------
        float2 pf_z2 = __ldcg((const float2*)&g_z[(m0 + rr2) * 512 + n02 + cc2]);

        // ---------- produce A = rh (tf32) ----------
        {
            const float* rrow = g_rh + (m0 + pr) * 512;
            #pragma unroll
            for (int j = 0; j < 16; j++) {
                int k = pc + 32 * j;
                float4 r4 = __ldcg((const float4*)(rrow + k));
                uint4 o;
                o.x = f2tf32(r4.x); o.y = f2tf32(r4.y);
                o.z = f2tf32(r4.z); o.w = f2tf32(r4.w);
                *(uint4*)&Ab[pr * AS + k] = o;
            }
        }
        __syncthreads();
        // ---------- GEMM2 (mma): 32x16, K-slice 64 per warp ----------
        {
            float acc[2][2][4];
            #pragma unroll
            for (int mt = 0; mt < 2; mt++)
                #pragma unroll
                for (int nt = 0; nt < 2; nt++)
                    #pragma unroll
                    for (int q = 0; q < 4; q++) acc[mt][nt][q] = 0.f;
            #pragma unroll
            for (int ks = 0; ks < 8; ks++) {
                int k = kbase + ks * 8;
                unsigned af[2][4];
                #pragma unroll
                for (int mt = 0; mt < 2; mt++) {
                    int mb = mt * 16;
                    af[mt][0] = Ab[(mb + g) * AS + k + tg];
                    af[mt][1] = Ab[(mb + g + 8) * AS + k + tg];
                    af[mt][2] = Ab[(mb + g) * AS + k + tg + 4];
                    af[mt][3] = Ab[(mb + g + 8) * AS + k + tg + 4];
                }
                unsigned bf[2][2];
                #pragma unroll
                for (int nt = 0; nt < 2; nt++) {
                    bf[nt][0] = Wh3t[(k + tg) * WS3 + nt * 8 + g];
                    bf[nt][1] = Wh3t[(k + tg + 4) * WS3 + nt * 8 + g];
                }
                #pragma unroll
                for (int mt = 0; mt < 2; mt++)
                    #pragma unroll
                    for (int nt = 0; nt < 2; nt++)
                        mma_tf32(acc[mt][nt], af[mt], bf[nt]);
            }
            #pragma unroll
            for (int mt = 0; mt < 2; mt++)
                #pragma unroll
                for (int nt = 0; nt < 2; nt++) {
                    float* base = &Red[kg * RKG2 + (mt * 16 + g) * RSTR2 + nt * 8 + tg * 2];
                    *(float2*)base = make_float2(acc[mt][nt][0], acc[mt][nt][1]);
                    *(float2*)(base + 8 * RSTR2) = make_float2(acc[mt][nt][2], acc[mt][nt][3]);
                }
        }
        __syncthreads();
        // ---------- red2: reduce + gates + h update ----------
        {
            float2 s = *(float2*)&Red[rr2 * RSTR2 + cc2];
            #pragma unroll
            for (int q = 1; q < 8; q++) {
                float2 v = *(float2*)&Red[q * RKG2 + rr2 * RSTR2 + cc2];
                s.x += v.x; s.y += v.y;
            }
            int b = m0 + rr2, n = n02 + cc2;
            float ht0 = tanhf(s.x + pf_pre2.x), ht1 = tanhf(s.y + pf_pre2.y);
            float hd0 = pf_gm2.x * pf_h2.x, hd1 = pf_gm2.y * pf_h2.y;
            float hn0 = (1.f - pf_z2.x) * hd0 + pf_z2.x * ht0;
            float hn1 = (1.f - pf_z2.y) * hd1 + pf_z2.y * ht1;
            *(float2*)&g_h[b * 512 + n] = make_float2(hn0, hn1);
            *(float2*)&g_hseq[(size_t)(b * Ldim + step) * 512 + n] = make_float2(hn0, hn1);
        }
        // ---------- preload gamma(step+1) into Ab (overlaps barrier) ----------
        if (step + 1 < Ldim) {
            const float* grow = g_gammah + (size_t)((m0 + pr) * Ldim + step + 1) * 512;
            #pragma unroll
            for (int j = 0; j < 16; j++) {
                int k = pc + 32 * j;
                *(float4*)&Abf[pr * AS + k] = *(const float4*)(grow + k);
            }
        }
        groupbar(rg, tn);
    }
}

// ---------------- launch -----------------------------------------------------
extern "C" void kernel_launch(void* const* d_in, const int* in_sizes, int n_in,
                              void* d_out, int out_size) {
    const float* C     = (const float*)d_in[0];
    const float* t     = (const float*)d_in[1];
    const int*   mask  = (const int*)  d_in[2];
    const float* Wx    = (const float*)d_in[3];
    const float* Wh    = (const float*)d_in[4];
    const float* Wm    = (const float*)d_in[5];
    const float* bvec  = (const float*)d_in[6];
    const float* w_gx  = (const float*)d_in[7];
    const float* b_gx  = (const float*)d_in[8];
    const float* W_gh  = (const float*)d_in[9];
    const float* b_gh  = (const float*)d_in[10];
    const float* W_out = (const float*)d_in[11];
    const float* b_out = (const float*)d_in[12];
    float* out = (float*)d_out;

    cudaFuncSetAttribute(k_seq, cudaFuncAttributeMaxDynamicSharedMemorySize, SMEM_SEQ);

    k_xmean<<<Bdim * Hdim / 256, 256>>>(C, mask);
    k_scan <<<Bdim * Hdim / 256, 256>>>(C, t, mask, w_gx, b_gx);
    k_gh_mma <<<dim3(Hdim / 128, BL / 128), 256>>>(W_gh, b_gh);
    k_pre_mma<<<dim3(H3 / 128,  BL / 128), 256>>>(mask, Wx, Wm, bvec);
    k_seq<<<NBLK, 256, SMEM_SEQ>>>(Wh);
    k_out_mma<<<dim3(OUTD / 128, BL / 128), 256>>>(W_out, b_out, out);
}

// round 9
// speedup vs baseline: 1.0694x; 1.0694x over previous
#include <cuda_runtime.h>
#include <math.h>

#define Bdim 128
#define Ldim 256
#define Hdim 512
#define H3   1536
#define OUTD 256
#define BL   (Bdim*Ldim)   // 32768
#define NBLK 128

// ---------------- scratch (device globals) ----------------------------------
__device__ float g_xmean[Bdim*Hdim];
__device__ float g_delta[BL*Hdim];
__device__ float g_xhat [BL*Hdim];
__device__ float g_gammah[BL*Hdim];
__device__ float g_pre  [BL*H3];
__device__ float g_hseq [BL*Hdim];
__device__ float g_h    [Bdim*Hdim];
__device__ float g_z    [Bdim*Hdim];
__device__ float g_rh   [Bdim*Hdim];
__device__ unsigned g_arr4[4*32];
__device__ volatile unsigned g_rel4[4*32];

// ---------------- per-row-group barrier (32 blocks) -------------------------
// R7 structure; ONLY change this round: poll interval 32 -> 4 ns (wake-up
// latency on the serial chain).
__device__ __forceinline__ void groupbar(int rg) {
    __syncthreads();
    if (threadIdx.x == 0) {
        __threadfence();
        unsigned gen = g_rel4[rg * 32];
        if (atomicInc((unsigned*)&g_arr4[rg * 32], 31u) == 31u) {
            __threadfence();
            g_rel4[rg * 32] = gen + 1u;
        } else {
            while (g_rel4[rg * 32] == gen) { __nanosleep(4); }
        }
    }
    __syncthreads();
}

__device__ __forceinline__ float sigmoidf_(float x) { return 1.f / (1.f + expf(-x)); }

__device__ __forceinline__ unsigned f2tf32(float f) {
    unsigned r; asm("cvt.rna.tf32.f32 %0, %1;" : "=r"(r) : "f"(f)); return r;
}
__device__ __forceinline__ void mma_tf32(float* c, const unsigned* a, const unsigned* b) {
    asm volatile("mma.sync.aligned.m16n8k8.row.col.f32.tf32.tf32.f32 "
        "{%0,%1,%2,%3}, {%4,%5,%6,%7}, {%8,%9}, {%0,%1,%2,%3};"
        : "+f"(c[0]), "+f"(c[1]), "+f"(c[2]), "+f"(c[3])
        : "r"(a[0]), "r"(a[1]), "r"(a[2]), "r"(a[3]), "r"(b[0]), "r"(b[1]));
}

// ---------------- K1: x_mean -------------------------------------------------
__global__ void __launch_bounds__(256) k_xmean(const float* __restrict__ C,
                                               const int* __restrict__ mask) {
    int idx = blockIdx.x * 256 + threadIdx.x;
    int b = idx >> 9, h = idx & 511;
    const int* mp = mask + (size_t)b * Ldim * Hdim + h;
    float s = 0.f, cnt = 0.f;
    #pragma unroll 4
    for (int l = 0; l < Ldim; l++) {
        float m = (float)mp[l * Hdim];
        s   += m * C[l * Hdim + h];
        cnt += m;
    }
    g_xmean[idx] = s / fmaxf(cnt, 1.f);
}

// ---------------- K2: elementwise scans --------------------------------------
__global__ void __launch_bounds__(256) k_scan(const float* __restrict__ C,
                                              const float* __restrict__ t,
                                              const int* __restrict__ mask,
                                              const float* __restrict__ w_gx,
                                              const float* __restrict__ b_gx) {
    int idx = blockIdx.x * 256 + threadIdx.x;
    int b = idx >> 9, h = idx & 511;
    float xm = g_xmean[idx];
    float xl = xm, dprev = 0.f, mprev = 1.f, tprev = 0.f;
    float wg = w_gx[h], bg = b_gx[h];
    const int* mp = mask + (size_t)b * Ldim * Hdim + h;
    const float* tp = t + b * Ldim;
    for (int l = 0; l < Ldim; l++) {
        float tc = tp[l];
        float dt = (l == 0) ? 0.f : (tc - tprev);
        tprev = tc;
        float m = (float)mp[l * Hdim];
        float delta = dt + (1.f - mprev) * dprev;
        float gx = expf(-fmaxf(0.f, wg * delta + bg));
        float x  = C[(l << 9) + h];
        int gi = ((b * Ldim + l) << 9) + h;
        g_delta[gi] = delta;
        g_xhat[gi]  = m * x + (1.f - m) * (gx * xl + (1.f - gx) * xm);
        xl = m * x + (1.f - m) * xl;
        dprev = delta; mprev = m;
    }
}

// =============================================================================
// tf32 mma GEMMs — fragment-major A smem layout (LDS.128 fragment loads).
// =============================================================================
#define BSTR 136
#define AFRB 288
#define AFRW 2304

#define STORE_AFRAG(Abuf, base, v)                                  \
    do {                                                            \
        (Abuf)[(base) + 0]  = f2tf32((v).x);                        \
        (Abuf)[(base) + 8]  = f2tf32((v).y);                        \
        (Abuf)[(base) + 16] = f2tf32((v).z);                        \
        (Abuf)[(base) + 24] = f2tf32((v).w);                        \
    } while (0)

__global__ void __launch_bounds__(256, 2) k_gh_mma(const float* __restrict__ Bw,
                                                   const float* __restrict__ bias) {
    __shared__ __align__(16) unsigned Afr[2][AFRW];
    __shared__ unsigned Bs[2][16 * BSTR];
    const int tid = threadIdx.x;
    const int bn = blockIdx.x * 128, bm = blockIdx.y * 128;
    const int wid = tid >> 5, lane = tid & 31;
    const int wm = (wid >> 2) * 64, wn = (wid & 3) * 32;
    const int g = lane >> 2, tg = lane & 3;
    const int arow = tid >> 2, ac4 = (tid & 3) * 4;
    const int brow = tid >> 5, bc4 = lane * 4;
    const int abase0 = (arow >> 4) * AFRB + (arow & 7) * 36 + (ac4 >> 3) * 4
                     + ((arow >> 3) & 1) + ((ac4 >> 2) & 1) * 2;
    const int abase1 = abase0 + 4 * AFRB;
    const int mbkw = (wid >> 2) * 4;

    float acc[4][4][4];
    #pragma unroll
    for (int i = 0; i < 4; i++)
        #pragma unroll
        for (int j = 0; j < 4; j++)
            #pragma unroll
            for (int q = 0; q < 4; q++) acc[i][j][q] = 0.f;

    float4 av0, av1, bv0, bv1;
    av0 = *(const float4*)&g_delta[(size_t)(bm + arow) * Hdim + ac4];
    av1 = *(const float4*)&g_delta[(size_t)(bm + arow + 64) * Hdim + ac4];
    bv0 = *(const float4*)&Bw[(size_t)(brow) * Hdim + bn + bc4];
    bv1 = *(const float4*)&Bw[(size_t)(brow + 8) * Hdim + bn + bc4];
    {
        unsigned* A = Afr[0]; unsigned* B = Bs[0];
        STORE_AFRAG(A, abase0, av0);
        STORE_AFRAG(A, abase1, av1);
        B[brow * BSTR + bc4 + 0] = f2tf32(bv0.x); B[brow * BSTR + bc4 + 1] = f2tf32(bv0.y);
        B[brow * BSTR + bc4 + 2] = f2tf32(bv0.z); B[brow * BSTR + bc4 + 3] = f2tf32(bv0.w);
        B[(brow + 8) * BSTR + bc4 + 0] = f2tf32(bv1.x); B[(brow + 8) * BSTR + bc4 + 1] = f2tf32(bv1.y);
        B[(brow + 8) * BSTR + bc4 + 2] = f2tf32(bv1.z); B[(brow + 8) * BSTR + bc4 + 3] = f2tf32(bv1.w);
    }
    __syncthreads();

    const int KT = Hdim / 16;
    for (int kt = 0; kt < KT; kt++) {
        if (kt + 1 < KT) {
            int k0 = (kt + 1) * 16;
            av0 = *(const float4*)&g_delta[(size_t)(bm + arow) * Hdim + k0 + ac4];
            av1 = *(const float4*)&g_delta[(size_t)(bm + arow + 64) * Hdim + k0 + ac4];
            bv0 = *(const float4*)&Bw[(size_t)(k0 + brow) * Hdim + bn + bc4];
            bv1 = *(const float4*)&Bw[(size_t)(k0 + brow + 8) * Hdim + bn + bc4];
        }
        const unsigned* A = Afr[kt & 1];
        const unsigned* B = Bs[kt & 1];
        #pragma unroll
        for (int ks = 0; ks < 2; ks++) {
            unsigned af[4][4], bf[4][2];
            #pragma unroll
            for (int mt = 0; mt < 4; mt++) {
                uint4 fa = *(const uint4*)&A[(mbkw + mt) * AFRB + g * 36 + tg * 8 + ks * 4];
                af[mt][0] = fa.x; af[mt][1] = fa.y; af[mt][2] = fa.z; af[mt][3] = fa.w;
            }
            #pragma unroll
            for (int nt = 0; nt < 4; nt++) {
                int nb = wn + nt * 8;
                bf[nt][0] = B[(ks * 8 + tg) * BSTR + nb + g];
                bf[nt][1] = B[(ks * 8 + tg + 4) * BSTR + nb + g];
            }
            #pragma unroll
            for (int mt = 0; mt < 4; mt++)
                #pragma unroll
                for (int nt = 0; nt < 4; nt++)
                    mma_tf32(acc[mt][nt], af[mt], bf[nt]);
        }
        if (kt + 1 < KT) {
            unsigned* An = Afr[(kt + 1) & 1]; unsigned* Bn = Bs[(kt + 1) & 1];
            STORE_AFRAG(An, abase0, av0);
            STORE_AFRAG(An, abase1, av1);
            Bn[brow * BSTR + bc4 + 0] = f2tf32(bv0.x); Bn[brow * BSTR + bc4 + 1] = f2tf32(bv0.y);
            Bn[brow * BSTR + bc4 + 2] = f2tf32(bv0.z); Bn[brow * BSTR + bc4 + 3] = f2tf32(bv0.w);
            Bn[(brow + 8) * BSTR + bc4 + 0] = f2tf32(bv1.x); Bn[(brow + 8) * BSTR + bc4 + 1] = f2tf32(bv1.y);
            Bn[(brow + 8) * BSTR + bc4 + 2] = f2tf32(bv1.z); Bn[(brow + 8) * BSTR + bc4 + 3] = f2tf32(bv1.w);
        }
        __syncthreads();
    }

    #pragma unroll
    for (int mt = 0; mt < 4; mt++) {
        #pragma unroll
        for (int nt = 0; nt < 4; nt++) {
            int col = bn + wn + nt * 8 + tg * 2;
            float b0 = bias[col], b1 = bias[col + 1];
            int r0 = bm + wm + mt * 16 + g;
            float2 o0, o1;
            o0.x = expf(-fmaxf(0.f, acc[mt][nt][0] + b0));
            o0.y = expf(-fmaxf(0.f, acc[mt][nt][1] + b1));
            o1.x = expf(-fmaxf(0.f, acc[mt][nt][2] + b0));
            o1.y = expf(-fmaxf(0.f, acc[mt][nt][3] + b1));
            *(float2*)&g_gammah[(size_t)r0 * Hdim + col] = o0;
            *(float2*)&g_gammah[(size_t)(r0 + 8) * Hdim + col] = o1;
        }
    }
}

__global__ void __launch_bounds__(256, 2) k_pre_mma(const int* __restrict__ mask,
                                                    const float* __restrict__ Wx,
                                                    const float* __restrict__ Wm,
                                                    const float* __restrict__ bias) {
    __shared__ __align__(16) unsigned Afr[2][AFRW];
    __shared__ unsigned Bs[2][16 * BSTR];
    const int tid = threadIdx.x;
    const int bn = blockIdx.x * 128, bm = blockIdx.y * 128;
    const int wid = tid >> 5, lane = tid & 31;
    const int wm = (wid >> 2) * 64, wn = (wid & 3) * 32;
    const int g = lane >> 2, tg = lane & 3;
    const int arow = tid >> 2, ac4 = (tid & 3) * 4;
    const int brow = tid >> 5, bc4 = lane * 4;
    const int abase0 = (arow >> 4) * AFRB + (arow & 7) * 36 + (ac4 >> 3) * 4
                     + ((arow >> 3) & 1) + ((ac4 >> 2) & 1) * 2;
    const int abase1 = abase0 + 4 * AFRB;
    const int mbkw = (wid >> 2) * 4;

    float acc[4][4][4];
    #pragma unroll
    for (int i = 0; i < 4; i++)
        #pragma unroll
        for (int j = 0; j < 4; j++)
            #pragma unroll
            for (int q = 0; q < 4; q++) acc[i][j][q] = 0.f;

    float4 av0, av1, bv0, bv1;
    av0 = *(const float4*)&g_xhat[(size_t)(bm + arow) * Hdim + ac4];
    av1 = *(const float4*)&g_xhat[(size_t)(bm + arow + 64) * Hdim + ac4];
    bv0 = *(const float4*)&Wx[(size_t)(brow) * H3 + bn + bc4];
    bv1 = *(const float4*)&Wx[(size_t)(brow + 8) * H3 + bn + bc4];
    {
        unsigned* A = Afr[0]; unsigned* B = Bs[0];
        STORE_AFRAG(A, abase0, av0);
        STORE_AFRAG(A, abase1, av1);
        B[brow * BSTR + bc4 + 0] = f2tf32(bv0.x); B[brow * BSTR + bc4 + 1] = f2tf32(bv0.y);
        B[brow * BSTR + bc4 + 2] = f2tf32(bv0.z); B[brow * BSTR + bc4 + 3] = f2tf32(bv0.w);
        B[(brow + 8) * BSTR + bc4 + 0] = f2tf32(bv1.x); B[(brow + 8) * BSTR + bc4 + 1] = f2tf32(bv1.y);
        B[(brow + 8) * BSTR + bc4 + 2] = f2tf32(bv1.z); B[(brow + 8) * BSTR + bc4 + 3] = f2tf32(bv1.w);
    }
    __syncthreads();

    const int KT = 64;
    for (int kt = 0; kt < KT; kt++) {
        if (kt + 1 < KT) {
            int nkt = kt + 1;
            int k0 = (nkt & 31) * 16;
            if (nkt < 32) {
                av0 = *(const float4*)&g_xhat[(size_t)(bm + arow) * Hdim + k0 + ac4];
                av1 = *(const float4*)&g_xhat[(size_t)(bm + arow + 64) * Hdim + k0 + ac4];
                bv0 = *(const float4*)&Wx[(size_t)(k0 + brow) * H3 + bn + bc4];
                bv1 = *(const float4*)&Wx[(size_t)(k0 + brow + 8) * H3 + bn + bc4];
            } else {
                int4 m0 = *(const int4*)&mask[(size_t)(bm + arow) * Hdim + k0 + ac4];
                int4 m1 = *(const int4*)&mask[(size_t)(bm + arow + 64) * Hdim + k0 + ac4];
                av0 = make_float4((float)m0.x, (float)m0.y, (float)m0.z, (float)m0.w);
                av1 = make_float4((float)m1.x, (float)m1.y, (float)m1.z, (float)m1.w);
                bv0 = *(const float4*)&Wm[(size_t)(k0 + brow) * H3 + bn + bc4];
                bv1 = *(const float4*)&Wm[(size_t)(k0 + brow + 8) * H3 + bn + bc4];
            }
        }
        const unsigned* A = Afr[kt & 1];
        const unsigned* B = Bs[kt & 1];
        #pragma unroll
        for (int ks = 0; ks < 2; ks++) {
            unsigned af[4][4], bf[4][2];
            #pragma unroll
            for (int mt = 0; mt < 4; mt++) {
                uint4 fa = *(const uint4*)&A[(mbkw + mt) * AFRB + g * 36 + tg * 8 + ks * 4];
                af[mt][0] = fa.x; af[mt][1] = fa.y; af[mt][2] = fa.z; af[mt][3] = fa.w;
            }
            #pragma unroll
            for (int nt = 0; nt < 4; nt++) {
                int nb = wn + nt * 8;
                bf[nt][0] = B[(ks * 8 + tg) * BSTR + nb + g];
                bf[nt][1] = B[(ks * 8 + tg + 4) * BSTR + nb + g];
            }
            #pragma unroll
            for (int mt = 0; mt < 4; mt++)
                #pragma unroll
                for (int nt = 0; nt < 4; nt++)
                    mma_tf32(acc[mt][nt], af[mt], bf[nt]);
        }
        if (kt + 1 < KT) {
            unsigned* An = Afr[(kt + 1) & 1]; unsigned* Bn = Bs[(kt + 1) & 1];
            STORE_AFRAG(An, abase0, av0);
            STORE_AFRAG(An, abase1, av1);
            Bn[brow * BSTR + bc4 + 0] = f2tf32(bv0.x); Bn[brow * BSTR + bc4 + 1] = f2tf32(bv0.y);
            Bn[brow * BSTR + bc4 + 2] = f2tf32(bv0.z); Bn[brow * BSTR + bc4 + 3] = f2tf32(bv0.w);
            Bn[(brow + 8) * BSTR + bc4 + 0] = f2tf32(bv1.x); Bn[(brow + 8) * BSTR + bc4 + 1] = f2tf32(bv1.y);
            Bn[(brow + 8) * BSTR + bc4 + 2] = f2tf32(bv1.z); Bn[(brow + 8) * BSTR + bc4 + 3] = f2tf32(bv1.w);
        }
        __syncthreads();
    }

    #pragma unroll
    for (int mt = 0; mt < 4; mt++) {
        #pragma unroll
        for (int nt = 0; nt < 4; nt++) {
            int col = bn + wn + nt * 8 + tg * 2;
            float b0 = bias[col], b1 = bias[col + 1];
            int r0 = bm + wm + mt * 16 + g;
            float2 o0, o1;
            o0.x = acc[mt][nt][0] + b0; o0.y = acc[mt][nt][1] + b1;
            o1.x = acc[mt][nt][2] + b0; o1.y = acc[mt][nt][3] + b1;
            *(float2*)&g_pre[(size_t)r0 * H3 + col] = o0;
            *(float2*)&g_pre[(size_t)(r0 + 8) * H3 + col] = o1;
        }
    }
}

// ---------------- K6 (mma): out = h_seq @ W_out + b_out ----------------------
__global__ void __launch_bounds__(256, 2) k_out_mma(const float* __restrict__ Bw,
                                                    const float* __restrict__ bias,
                                                    float* __restrict__ out) {
    __shared__ __align__(16) unsigned Afr[2][AFRW];
    __shared__ unsigned Bs[2][16 * BSTR];
    const int tid = threadIdx.x;
    const int bn = blockIdx.x * 128, bm = blockIdx.y * 128;
    const int wid = tid >> 5, lane = tid & 31;
    const int wm = (wid >> 2) * 64, wn = (wid & 3) * 32;
    const int g = lane >> 2, tg = lane & 3;
    const int arow = tid >> 2, ac4 = (tid & 3) * 4;
    const int brow = tid >> 5, bc4 = lane * 4;
    const int abase0 = (arow >> 4) * AFRB + (arow & 7) * 36 + (ac4 >> 3) * 4
                     + ((arow >> 3) & 1) + ((ac4 >> 2) & 1) * 2;
    const int abase1 = abase0 + 4 * AFRB;
    const int mbkw = (wid >> 2) * 4;

    float acc[4][4][4];
    #pragma unroll
    for (int i = 0; i < 4; i++)
        #pragma unroll
        for (int j = 0; j < 4; j++)
            #pragma unroll
            for (int q = 0; q < 4; q++) acc[i][j][q] = 0.f;

    float4 av0, av1, bv0, bv1;
    av0 = *(const float4*)&g_hseq[(size_t)(bm + arow) * Hdim + ac4];
    av1 = *(const float4*)&g_hseq[(size_t)(bm + arow + 64) * Hdim + ac4];
    bv0 = *(const float4*)&Bw[(size_t)(brow) * OUTD + bn + bc4];
    bv1 = *(const float4*)&Bw[(size_t)(brow + 8) * OUTD + bn + bc4];
    {
        unsigned* A = Afr[0]; unsigned* B = Bs[0];
        STORE_AFRAG(A, abase0, av0);
        STORE_AFRAG(A, abase1, av1);
        B[brow * BSTR + bc4 + 0] = f2tf32(bv0.x); B[brow * BSTR + bc4 + 1] = f2tf32(bv0.y);
        B[brow * BSTR + bc4 + 2] = f2tf32(bv0.z); B[brow * BSTR + bc4 + 3] = f2tf32(bv0.w);
        B[(brow + 8) * BSTR + bc4 + 0] = f2tf32(bv1.x); B[(brow + 8) * BSTR + bc4 + 1] = f2tf32(bv1.y);
        B[(brow + 8) * BSTR + bc4 + 2] = f2tf32(bv1.z); B[(brow + 8) * BSTR + bc4 + 3] = f2tf32(bv1.w);
    }
    __syncthreads();

    const int KT = Hdim / 16;
    for (int kt = 0; kt < KT; kt++) {
        if (kt + 1 < KT) {
            int k0 = (kt + 1) * 16;
            av0 = *(const float4*)&g_hseq[(size_t)(bm + arow) * Hdim + k0 + ac4];
            av1 = *(const float4*)&g_hseq[(size_t)(bm + arow + 64) * Hdim + k0 + ac4];
            bv0 = *(const float4*)&Bw[(size_t)(k0 + brow) * OUTD + bn + bc4];
            bv1 = *(const float4*)&Bw[(size_t)(k0 + brow + 8) * OUTD + bn + bc4];
        }
        const unsigned* A = Afr[kt & 1];
        const unsigned* B = Bs[kt & 1];
        #pragma unroll
        for (int ks = 0; ks < 2; ks++) {
            unsigned af[4][4], bf[4][2];
            #pragma unroll
            for (int mt = 0; mt < 4; mt++) {
                uint4 fa = *(const uint4*)&A[(mbkw + mt) * AFRB + g * 36 + tg * 8 + ks * 4];
                af[mt][0] = fa.x; af[mt][1] = fa.y; af[mt][2] = fa.z; af[mt][3] = fa.w;
            }
            #pragma unroll
            for (int nt = 0; nt < 4; nt++) {
                int nb = wn + nt * 8;
                bf[nt][0] = B[(ks * 8 + tg) * BSTR + nb + g];
                bf[nt][1] = B[(ks * 8 + tg + 4) * BSTR + nb + g];
            }
            #pragma unroll
            for (int mt = 0; mt < 4; mt++)
                #pragma unroll
                for (int nt = 0; nt < 4; nt++)
                    mma_tf32(acc[mt][nt], af[mt], bf[nt]);
        }
        if (kt + 1 < KT) {
            unsigned* An = Afr[(kt + 1) & 1]; unsigned* Bn = Bs[(kt + 1) & 1];
            STORE_AFRAG(An, abase0, av0);
            STORE_AFRAG(An, abase1, av1);
            Bn[brow * BSTR + bc4 + 0] = f2tf32(bv0.x); Bn[brow * BSTR + bc4 + 1] = f2tf32(bv0.y);
            Bn[brow * BSTR + bc4 + 2] = f2tf32(bv0.z); Bn[brow * BSTR + bc4 + 3] = f2tf32(bv0.w);
            Bn[(brow + 8) * BSTR + bc4 + 0] = f2tf32(bv1.x); Bn[(brow + 8) * BSTR + bc4 + 1] = f2tf32(bv1.y);
            Bn[(brow + 8) * BSTR + bc4 + 2] = f2tf32(bv1.z); Bn[(brow + 8) * BSTR + bc4 + 3] = f2tf32(bv1.w);
        }
        __syncthreads();
    }

    #pragma unroll
    for (int mt = 0; mt < 4; mt++) {
        #pragma unroll
        for (int nt = 0; nt < 4; nt++) {
            int col = bn + wn + nt * 8 + tg * 2;
            float b0 = bias[col], b1 = bias[col + 1];
            int r0 = bm + wm + mt * 16 + g;
            float2 o0, o1;
            o0.x = acc[mt][nt][0] + b0; o0.y = acc[mt][nt][1] + b1;
            o1.x = acc[mt][nt][2] + b0; o1.y = acc[mt][nt][3] + b1;
            *(float2*)&out[(size_t)r0 * OUTD + col] = o0;
            *(float2*)&out[(size_t)(r0 + 8) * OUTD + col] = o1;
        }
    }
}

// =============================================================================
// K5: persistent sequential recurrence — R7 structure + epilogue prefetch.
// =============================================================================
#define OFF_WH1 0
#define WS1     40
#define OFF_WH3 20480
#define WS3     20
#define OFF_AB  30720
#define AS      516
#define OFF_RED 47232
#define RSTR1   36
#define RKG1    (32*RSTR1)
#define RSTR2   20
#define RKG2    (32*RSTR2)
#define SMEM_SEQ ((OFF_RED + 8*RKG1) * 4)   // 225792 B

__global__ void __launch_bounds__(256, 1) k_seq(const float* __restrict__ Wh) {
    extern __shared__ unsigned smu[];
    unsigned* Wh1t = smu + OFF_WH1;
    unsigned* Wh3t = smu + OFF_WH3;
    unsigned* Ab   = smu + OFF_AB;
    float*    Red  = (float*)(smu + OFF_RED);

    const int tid = threadIdx.x;
    const int blk = blockIdx.x;
    const int rg  = blk >> 5;
    const int tn  = blk & 31;
    const int m0  = rg * 32;
    const int n0  = tn * 32;
    const int n02 = tn * 16;

    for (int i = tid; i < 512 * 32; i += 256) {
        int k = i >> 5, n = i & 31;
        Wh1t[k * WS1 + n] = f2tf32(Wh[(size_t)k * H3 + n0 + n]);
    }
    for (int i = tid; i < 512 * 16; i += 256) {
        int k = i >> 4, n = i & 15;
        Wh3t[k * WS3 + n] = f2tf32(Wh[(size_t)k * H3 + 1024 + n02 + n]);
    }
    if (tn == 0)
        for (int i = tid; i < 32 * 512; i += 256) g_h[m0 * 512 + i] = 0.f;
    groupbar(rg);

    const int lane = tid & 31, kg = tid >> 5;
    const int g = lane >> 2, tg = lane & 3;
    const int kbase = kg * 64;
    const int pr = tid >> 3, pc = (tid & 7) * 4;
    const int rr1 = tid >> 3, cc1 = (tid * 4) & 31;
    const int rr2 = tid >> 3, cc2 = (tid * 2) & 15;
    const int nn1 = (n0 >= 512 ? n0 - 512 : 0) + cc1;

    for (int step = 0; step < Ldim; step++) {
        // ---------- epilogue prefetches (overlap with produce+GEMM1) ----------
        float4 pf_pre4 = __ldcg((const float4*)&g_pre[(size_t)((m0 + rr1) * Ldim + step) * H3 + n0 + cc1]);
        float2 pf_pre2 = __ldcg((const float2*)&g_pre[(size_t)((m0 + rr2) * Ldim + step) * H3 + 1024 + n02 + cc2]);
        float2 pf_gm2  = *(const float2*)&g_gammah[(size_t)((m0 + rr2) * Ldim + step) * 512 + n02 + cc2];
        float2 pf_h2   = __ldcg((const float2*)&g_h[(m0 + rr2) * 512 + n02 + cc2]);
        float4 pf_gm1  = *(const float4*)&g_gammah[(size_t)((m0 + rr1) * Ldim + step) * 512 + nn1];
        float4 pf_h1   = __ldcg((const float4*)&g_h[(m0 + rr1) * 512 + nn1]);

        // ---------- produce A = gamma(step) ⊙ h (tf32) ----------
        {
            const float* hrow = g_h + (m0 + pr) * 512;
            const float* grow = g_gammah + (size_t)((m0 + pr) * Ldim + step) * 512;
            #pragma unroll
            for (int j = 0; j < 16; j++) {
                int k = pc + 32 * j;
                float4 h4 = __ldcg((const float4*)(hrow + k));
                float4 g4 = *(const float4*)(grow + k);
                uint4 o;
                o.x = f2tf32(h4.x * g4.x); o.y = f2tf32(h4.y * g4.y);
                o.z = f2tf32(h4.z * g4.z); o.w = f2tf32(h4.w * g4.w);
                *(uint4*)&Ab[pr * AS + k] = o;
            }
        }
        __syncthreads();
        // ---------- GEMM1 (mma): 32x32, K-slice 64 per warp ----------
        {
            float acc[2][4][4];
            #pragma unroll
            for (int mt = 0; mt < 2; mt++)
                #pragma unroll
                for (int nt = 0; nt < 4; nt++)
                    #pragma unroll
                    for (int q = 0; q < 4; q++) acc[mt][nt][q] = 0.f;
            #pragma unroll
            for (int ks = 0; ks < 8; ks++) {
                int k = kbase + ks * 8;
                unsigned af[2][4];
                #pragma unroll
                for (int mt = 0; mt < 2; mt++) {
                    int mb = mt * 16;
                    af[mt][0] = Ab[(mb + g) * AS + k + tg];
                    af[mt][1] = Ab[(mb + g + 8) * AS + k + tg];
                    af[mt][2] = Ab[(mb + g) * AS + k + tg + 4];
                    af[mt][3] = Ab[(mb + g + 8) * AS + k + tg + 4];
                }
                unsigned bf[4][2];
                #pragma unroll
                for (int nt = 0; nt < 4; nt++) {
                    bf[nt][0] = Wh1t[(k + tg) * WS1 + nt * 8 + g];
                    bf[nt][1] = Wh1t[(k + tg + 4) * WS1 + nt * 8 + g];
                }
                #pragma unroll
                for (int mt = 0; mt < 2; mt++)
                    #pragma unroll
                    for (int nt = 0; nt < 4; nt++)
                        mma_tf32(acc[mt][nt], af[mt], bf[nt]);
            }
            #pragma unroll
            for (int mt = 0; mt < 2; mt++)
                #pragma unroll
                for (int nt = 0; nt < 4; nt++) {
                    float* base = &Red[kg * RKG1 + (mt * 16 + g) * RSTR1 + nt * 8 + tg * 2];
                    *(float2*)base = make_float2(acc[mt][nt][0], acc[mt][nt][1]);
                    *(float2*)(base + 8 * RSTR1) = make_float2(acc[mt][nt][2], acc[mt][nt][3]);
                }
        }
        __syncthreads();
        // ---------- red1: reduce + sigmoid; z or rh ----------
        {
            float4 s = *(float4*)&Red[rr1 * RSTR1 + cc1];
            #pragma unroll
            for (int q = 1; q < 8; q++) {
                float4 v = *(float4*)&Red[q * RKG1 + rr1 * RSTR1 + cc1];
                s.x += v.x; s.y += v.y; s.z += v.z; s.w += v.w;
            }
            int b = m0 + rr1;
            float s0 = sigmoidf_(s.x + pf_pre4.x);
            float s1 = sigmoidf_(s.y + pf_pre4.y);
            float s2 = sigmoidf_(s.z + pf_pre4.z);
            float s3 = sigmoidf_(s.w + pf_pre4.w);
            if (n0 < 512) {
                *(float4*)&g_z[b * 512 + n0 + cc1] = make_float4(s0, s1, s2, s3);
            } else {
                *(float4*)&g_rh[b * 512 + nn1] = make_float4(
                    s0 * pf_gm1.x * pf_h1.x, s1 * pf_gm1.y * pf_h1.y,
                    s2 * pf_gm1.z * pf_h1.z, s3 * pf_gm1.w * pf_h1.w);
            }
        }
        groupbar(rg);

        // ---------- post-barrier prefetch: z ----------
        float2 pf_z2 = __ldcg((const float2*)&g_z[(m0 + rr2) * 512 + n02 + cc2]);

        // ---------- produce A = rh (tf32) ----------
        {
            const float* rrow = g_rh + (m0 + pr) * 512;
            #pragma unroll
            for (int j = 0; j < 16; j++) {
                int k = pc + 32 * j;
                float4 r4 = __ldcg((const float4*)(rrow + k));
                uint4 o;
                o.x = f2tf32(r4.x); o.y = f2tf32(r4.y);
                o.z = f2tf32(r4.z); o.w = f2tf32(r4.w);
                *(uint4*)&Ab[pr * AS + k] = o;
            }
        }
        __syncthreads();
        // ---------- GEMM2 (mma): 32x16, K-slice 64 per warp ----------
        {
            float acc[2][2][4];
            #pragma unroll
            for (int mt = 0; mt < 2; mt++)
                #pragma unroll
                for (int nt = 0; nt < 2; nt++)
                    #pragma unroll
                    for (int q = 0; q < 4; q++) acc[mt][nt][q] = 0.f;
            #pragma unroll
            for (int ks = 0; ks < 8; ks++) {
                int k = kbase + ks * 8;
                unsigned af[2][4];
                #pragma unroll
                for (int mt = 0; mt < 2; mt++) {
                    int mb = mt * 16;
                    af[mt][0] = Ab[(mb + g) * AS + k + tg];
                    af[mt][1] = Ab[(mb + g + 8) * AS + k + tg];
                    af[mt][2] = Ab[(mb + g) * AS + k + tg + 4];
                    af[mt][3] = Ab[(mb + g + 8) * AS + k + tg + 4];
                }
                unsigned bf[2][2];
                #pragma unroll
                for (int nt = 0; nt < 2; nt++) {
                    bf[nt][0] = Wh3t[(k + tg) * WS3 + nt * 8 + g];
                    bf[nt][1] = Wh3t[(k + tg + 4) * WS3 + nt * 8 + g];
                }
                #pragma unroll
                for (int mt = 0; mt < 2; mt++)
                    #pragma unroll
                    for (int nt = 0; nt < 2; nt++)
                        mma_tf32(acc[mt][nt], af[mt], bf[nt]);
            }
            #pragma unroll
            for (int mt = 0; mt < 2; mt++)
                #pragma unroll
                for (int nt = 0; nt < 2; nt++) {
                    float* base = &Red[kg * RKG2 + (mt * 16 + g) * RSTR2 + nt * 8 + tg * 2];
                    *(float2*)base = make_float2(acc[mt][nt][0], acc[mt][nt][1]);
                    *(float2*)(base + 8 * RSTR2) = make_float2(acc[mt][nt][2], acc[mt][nt][3]);
                }
        }
        __syncthreads();
        // ---------- red2: reduce + gates + h update ----------
        {
            float2 s = *(float2*)&Red[rr2 * RSTR2 + cc2];
            #pragma unroll
            for (int q = 1; q < 8; q++) {
                float2 v = *(float2*)&Red[q * RKG2 + rr2 * RSTR2 + cc2];
                s.x += v.x; s.y += v.y;
            }
            int b = m0 + rr2, n = n02 + cc2;
            float ht0 = tanhf(s.x + pf_pre2.x), ht1 = tanhf(s.y + pf_pre2.y);
            float hd0 = pf_gm2.x * pf_h2.x, hd1 = pf_gm2.y * pf_h2.y;
            float hn0 = (1.f - pf_z2.x) * hd0 + pf_z2.x * ht0;
            float hn1 = (1.f - pf_z2.y) * hd1 + pf_z2.y * ht1;
            *(float2*)&g_h[b * 512 + n] = make_float2(hn0, hn1);
            *(float2*)&g_hseq[(size_t)(b * Ldim + step) * 512 + n] = make_float2(hn0, hn1);
        }
        groupbar(rg);
    }
}

// ---------------- launch -----------------------------------------------------
extern "C" void kernel_launch(void* const* d_in, const int* in_sizes, int n_in,
                              void* d_out, int out_size) {
    const float* C     = (const float*)d_in[0];
    const float* t     = (const float*)d_in[1];
    const int*   mask  = (const int*)  d_in[2];
    const float* Wx    = (const float*)d_in[3];
    const float* Wh    = (const float*)d_in[4];
    const float* Wm    = (const float*)d_in[5];
    const float* bvec  = (const float*)d_in[6];
    const float* w_gx  = (const float*)d_in[7];
    const float* b_gx  = (const float*)d_in[8];
    const float* W_gh  = (const float*)d_in[9];
    const float* b_gh  = (const float*)d_in[10];
    const float* W_out = (const float*)d_in[11];
    const float* b_out = (const float*)d_in[12];
    float* out = (float*)d_out;

    cudaFuncSetAttribute(k_seq, cudaFuncAttributeMaxDynamicSharedMemorySize, SMEM_SEQ);

    k_xmean<<<Bdim * Hdim / 256, 256>>>(C, mask);
    k_scan <<<Bdim * Hdim / 256, 256>>>(C, t, mask, w_gx, b_gx);
    k_gh_mma <<<dim3(Hdim / 128, BL / 128), 256>>>(W_gh, b_gh);
    k_pre_mma<<<dim3(H3 / 128,  BL / 128), 256>>>(mask, Wx, Wm, bvec);
    k_seq<<<NBLK, 256, SMEM_SEQ>>>(Wh);
    k_out_mma<<<dim3(OUTD / 128, BL / 128), 256>>>(W_out, b_out, out);
}

// round 10
// speedup vs baseline: 1.2811x; 1.1980x over previous
#include <cuda_runtime.h>
#include <cuda_fp16.h>
#include <math.h>

#define Bdim 128
#define Ldim 256
#define Hdim 512
#define H3   1536
#define OUTD 256
#define BL   (Bdim*Ldim)   // 32768
#define NBLK 128

// ---------------- scratch (device globals) ----------------------------------
__device__ float g_xmean[Bdim*Hdim];
__device__ float g_delta[BL*Hdim];
__device__ float g_xhat [BL*Hdim];
__device__ __align__(16) __half g_gammah[BL*Hdim];     // fp16 gamma_h
__device__ float g_pre  [BL*H3];
__device__ float g_hseq [BL*Hdim];
__device__ float g_h    [Bdim*Hdim];
__device__ float g_z    [Bdim*Hdim];
__device__ __align__(16) __half g_rh[Bdim*Hdim];       // fp16 r*gamma*h
__device__ unsigned g_arr4[4*32];
__device__ volatile unsigned g_rel4[4*32];

// ---------------- per-row-group barrier (32 blocks) -------------------------
__device__ __forceinline__ void groupbar(int rg) {
    __syncthreads();
    if (threadIdx.x == 0) {
        __threadfence();
        unsigned gen = g_rel4[rg * 32];
        if (atomicInc((unsigned*)&g_arr4[rg * 32], 31u) == 31u) {
            __threadfence();
            g_rel4[rg * 32] = gen + 1u;
        } else {
            while (g_rel4[rg * 32] == gen) { __nanosleep(4); }
        }
    }
    __syncthreads();
}

__device__ __forceinline__ float sigmoidf_(float x) { return 1.f / (1.f + expf(-x)); }

__device__ __forceinline__ unsigned f2tf32(float f) {
    unsigned r; asm("cvt.rna.tf32.f32 %0, %1;" : "=r"(r) : "f"(f)); return r;
}
__device__ __forceinline__ void mma_tf32(float* c, const unsigned* a, const unsigned* b) {
    asm volatile("mma.sync.aligned.m16n8k8.row.col.f32.tf32.tf32.f32 "
        "{%0,%1,%2,%3}, {%4,%5,%6,%7}, {%8,%9}, {%0,%1,%2,%3};"
        : "+f"(c[0]), "+f"(c[1]), "+f"(c[2]), "+f"(c[3])
        : "r"(a[0]), "r"(a[1]), "r"(a[2]), "r"(a[3]), "r"(b[0]), "r"(b[1]));
}
__device__ __forceinline__ void mma_f16(float* c, const unsigned* a, const unsigned* b) {
    asm volatile("mma.sync.aligned.m16n8k16.row.col.f32.f16.f16.f32 "
        "{%0,%1,%2,%3}, {%4,%5,%6,%7}, {%8,%9}, {%0,%1,%2,%3};"
        : "+f"(c[0]), "+f"(c[1]), "+f"(c[2]), "+f"(c[3])
        : "r"(a[0]), "r"(a[1]), "r"(a[2]), "r"(a[3]), "r"(b[0]), "r"(b[1]));
}
__device__ __forceinline__ unsigned pack_h2(float a, float b) {
    __half2 h = __floats2half2_rn(a, b);
    return *(unsigned*)&h;
}
__device__ __forceinline__ float2 h2f2(unsigned u) {
    __half2 h = *(__half2*)&u;
    return __half22float2(h);
}

// ---------------- K1: x_mean -------------------------------------------------
__global__ void __launch_bounds__(256) k_xmean(const float* __restrict__ C,
                                               const int* __restrict__ mask) {
    int idx = blockIdx.x * 256 + threadIdx.x;
    int b = idx >> 9, h = idx & 511;
    const int* mp = mask + (size_t)b * Ldim * Hdim + h;
    float s = 0.f, cnt = 0.f;
    #pragma unroll 4
    for (int l = 0; l < Ldim; l++) {
        float m = (float)mp[l * Hdim];
        s   += m * C[l * Hdim + h];
        cnt += m;
    }
    g_xmean[idx] = s / fmaxf(cnt, 1.f);
}

// ---------------- K2: elementwise scans --------------------------------------
__global__ void __launch_bounds__(256) k_scan(const float* __restrict__ C,
                                              const float* __restrict__ t,
                                              const int* __restrict__ mask,
                                              const float* __restrict__ w_gx,
                                              const float* __restrict__ b_gx) {
    int idx = blockIdx.x * 256 + threadIdx.x;
    int b = idx >> 9, h = idx & 511;
    float xm = g_xmean[idx];
    float xl = xm, dprev = 0.f, mprev = 1.f, tprev = 0.f;
    float wg = w_gx[h], bg = b_gx[h];
    const int* mp = mask + (size_t)b * Ldim * Hdim + h;
    const float* tp = t + b * Ldim;
    for (int l = 0; l < Ldim; l++) {
        float tc = tp[l];
        float dt = (l == 0) ? 0.f : (tc - tprev);
        tprev = tc;
        float m = (float)mp[l * Hdim];
        float delta = dt + (1.f - mprev) * dprev;
        float gx = expf(-fmaxf(0.f, wg * delta + bg));
        float x  = C[(l << 9) + h];
        int gi = ((b * Ldim + l) << 9) + h;
        g_delta[gi] = delta;
        g_xhat[gi]  = m * x + (1.f - m) * (gx * xl + (1.f - gx) * xm);
        xl = m * x + (1.f - m) * xl;
        dprev = delta; mprev = m;
    }
}

// =============================================================================
// tf32 mma GEMMs — fragment-major A smem layout (unchanged from R9)
// =============================================================================
#define BSTR 136
#define AFRB 288
#define AFRW 2304

#define STORE_AFRAG(Abuf, base, v)                                  \
    do {                                                            \
        (Abuf)[(base) + 0]  = f2tf32((v).x);                        \
        (Abuf)[(base) + 8]  = f2tf32((v).y);                        \
        (Abuf)[(base) + 16] = f2tf32((v).z);                        \
        (Abuf)[(base) + 24] = f2tf32((v).w);                        \
    } while (0)

__global__ void __launch_bounds__(256, 2) k_gh_mma(const float* __restrict__ Bw,
                                                   const float* __restrict__ bias) {
    __shared__ __align__(16) unsigned Afr[2][AFRW];
    __shared__ unsigned Bs[2][16 * BSTR];
    const int tid = threadIdx.x;
    const int bn = blockIdx.x * 128, bm = blockIdx.y * 128;
    const int wid = tid >> 5, lane = tid & 31;
    const int wm = (wid >> 2) * 64, wn = (wid & 3) * 32;
    const int g = lane >> 2, tg = lane & 3;
    const int arow = tid >> 2, ac4 = (tid & 3) * 4;
    const int brow = tid >> 5, bc4 = lane * 4;
    const int abase0 = (arow >> 4) * AFRB + (arow & 7) * 36 + (ac4 >> 3) * 4
                     + ((arow >> 3) & 1) + ((ac4 >> 2) & 1) * 2;
    const int abase1 = abase0 + 4 * AFRB;
    const int mbkw = (wid >> 2) * 4;

    float acc[4][4][4];
    #pragma unroll
    for (int i = 0; i < 4; i++)
        #pragma unroll
        for (int j = 0; j < 4; j++)
            #pragma unroll
            for (int q = 0; q < 4; q++) acc[i][j][q] = 0.f;

    float4 av0, av1, bv0, bv1;
    av0 = *(const float4*)&g_delta[(size_t)(bm + arow) * Hdim + ac4];
    av1 = *(const float4*)&g_delta[(size_t)(bm + arow + 64) * Hdim + ac4];
    bv0 = *(const float4*)&Bw[(size_t)(brow) * Hdim + bn + bc4];
    bv1 = *(const float4*)&Bw[(size_t)(brow + 8) * Hdim + bn + bc4];
    {
        unsigned* A = Afr[0]; unsigned* B = Bs[0];
        STORE_AFRAG(A, abase0, av0);
        STORE_AFRAG(A, abase1, av1);
        B[brow * BSTR + bc4 + 0] = f2tf32(bv0.x); B[brow * BSTR + bc4 + 1] = f2tf32(bv0.y);
        B[brow * BSTR + bc4 + 2] = f2tf32(bv0.z); B[brow * BSTR + bc4 + 3] = f2tf32(bv0.w);
        B[(brow + 8) * BSTR + bc4 + 0] = f2tf32(bv1.x); B[(brow + 8) * BSTR + bc4 + 1] = f2tf32(bv1.y);
        B[(brow + 8) * BSTR + bc4 + 2] = f2tf32(bv1.z); B[(brow + 8) * BSTR + bc4 + 3] = f2tf32(bv1.w);
    }
    __syncthreads();

    const int KT = Hdim / 16;
    for (int kt = 0; kt < KT; kt++) {
        if (kt + 1 < KT) {
            int k0 = (kt + 1) * 16;
            av0 = *(const float4*)&g_delta[(size_t)(bm + arow) * Hdim + k0 + ac4];
            av1 = *(const float4*)&g_delta[(size_t)(bm + arow + 64) * Hdim + k0 + ac4];
            bv0 = *(const float4*)&Bw[(size_t)(k0 + brow) * Hdim + bn + bc4];
            bv1 = *(const float4*)&Bw[(size_t)(k0 + brow + 8) * Hdim + bn + bc4];
        }
        const unsigned* A = Afr[kt & 1];
        const unsigned* B = Bs[kt & 1];
        #pragma unroll
        for (int ks = 0; ks < 2; ks++) {
            unsigned af[4][4], bf[4][2];
            #pragma unroll
            for (int mt = 0; mt < 4; mt++) {
                uint4 fa = *(const uint4*)&A[(mbkw + mt) * AFRB + g * 36 + tg * 8 + ks * 4];
                af[mt][0] = fa.x; af[mt][1] = fa.y; af[mt][2] = fa.z; af[mt][3] = fa.w;
            }
            #pragma unroll
            for (int nt = 0; nt < 4; nt++) {
                int nb = wn + nt * 8;
                bf[nt][0] = B[(ks * 8 + tg) * BSTR + nb + g];
                bf[nt][1] = B[(ks * 8 + tg + 4) * BSTR + nb + g];
            }
            #pragma unroll
            for (int mt = 0; mt < 4; mt++)
                #pragma unroll
                for (int nt = 0; nt < 4; nt++)
                    mma_tf32(acc[mt][nt], af[mt], bf[nt]);
        }
        if (kt + 1 < KT) {
            unsigned* An = Afr[(kt + 1) & 1]; unsigned* Bn = Bs[(kt + 1) & 1];
            STORE_AFRAG(An, abase0, av0);
            STORE_AFRAG(An, abase1, av1);
            Bn[brow * BSTR + bc4 + 0] = f2tf32(bv0.x); Bn[brow * BSTR + bc4 + 1] = f2tf32(bv0.y);
            Bn[brow * BSTR + bc4 + 2] = f2tf32(bv0.z); Bn[brow * BSTR + bc4 + 3] = f2tf32(bv0.w);
            Bn[(brow + 8) * BSTR + bc4 + 0] = f2tf32(bv1.x); Bn[(brow + 8) * BSTR + bc4 + 1] = f2tf32(bv1.y);
            Bn[(brow + 8) * BSTR + bc4 + 2] = f2tf32(bv1.z); Bn[(brow + 8) * BSTR + bc4 + 3] = f2tf32(bv1.w);
        }
        __syncthreads();
    }

    // epilogue: gamma_h as fp16
    #pragma unroll
    for (int mt = 0; mt < 4; mt++) {
        #pragma unroll
        for (int nt = 0; nt < 4; nt++) {
            int col = bn + wn + nt * 8 + tg * 2;
            float b0 = bias[col], b1 = bias[col + 1];
            int r0 = bm + wm + mt * 16 + g;
            float e00 = expf(-fmaxf(0.f, acc[mt][nt][0] + b0));
            float e01 = expf(-fmaxf(0.f, acc[mt][nt][1] + b1));
            float e10 = expf(-fmaxf(0.f, acc[mt][nt][2] + b0));
            float e11 = expf(-fmaxf(0.f, acc[mt][nt][3] + b1));
            *(unsigned*)&g_gammah[(size_t)r0 * Hdim + col] = pack_h2(e00, e01);
            *(unsigned*)&g_gammah[(size_t)(r0 + 8) * Hdim + col] = pack_h2(e10, e11);
        }
    }
}

__global__ void __launch_bounds__(256, 2) k_pre_mma(const int* __restrict__ mask,
                                                    const float* __restrict__ Wx,
                                                    const float* __restrict__ Wm,
                                                    const float* __restrict__ bias) {
    __shared__ __align__(16) unsigned Afr[2][AFRW];
    __shared__ unsigned Bs[2][16 * BSTR];
    const int tid = threadIdx.x;
    const int bn = blockIdx.x * 128, bm = blockIdx.y * 128;
    const int wid = tid >> 5, lane = tid & 31;
    const int wm = (wid >> 2) * 64, wn = (wid & 3) * 32;
    const int g = lane >> 2, tg = lane & 3;
    const int arow = tid >> 2, ac4 = (tid & 3) * 4;
    const int brow = tid >> 5, bc4 = lane * 4;
    const int abase0 = (arow >> 4) * AFRB + (arow & 7) * 36 + (ac4 >> 3) * 4
                     + ((arow >> 3) & 1) + ((ac4 >> 2) & 1) * 2;
    const int abase1 = abase0 + 4 * AFRB;
    const int mbkw = (wid >> 2) * 4;

    float acc[4][4][4];
    #pragma unroll
    for (int i = 0; i < 4; i++)
        #pragma unroll
        for (int j = 0; j < 4; j++)
            #pragma unroll
            for (int q = 0; q < 4; q++) acc[i][j][q] = 0.f;

    float4 av0, av1, bv0, bv1;
    av0 = *(const float4*)&g_xhat[(size_t)(bm + arow) * Hdim + ac4];
    av1 = *(const float4*)&g_xhat[(size_t)(bm + arow + 64) * Hdim + ac4];
    bv0 = *(const float4*)&Wx[(size_t)(brow) * H3 + bn + bc4];
    bv1 = *(const float4*)&Wx[(size_t)(brow + 8) * H3 + bn + bc4];
    {
        unsigned* A = Afr[0]; unsigned* B = Bs[0];
        STORE_AFRAG(A, abase0, av0);
        STORE_AFRAG(A, abase1, av1);
        B[brow * BSTR + bc4 + 0] = f2tf32(bv0.x); B[brow * BSTR + bc4 + 1] = f2tf32(bv0.y);
        B[brow * BSTR + bc4 + 2] = f2tf32(bv0.z); B[brow * BSTR + bc4 + 3] = f2tf32(bv0.w);
        B[(brow + 8) * BSTR + bc4 + 0] = f2tf32(bv1.x); B[(brow + 8) * BSTR + bc4 + 1] = f2tf32(bv1.y);
        B[(brow + 8) * BSTR + bc4 + 2] = f2tf32(bv1.z); B[(brow + 8) * BSTR + bc4 + 3] = f2tf32(bv1.w);
    }
    __syncthreads();

    const int KT = 64;
    for (int kt = 0; kt < KT; kt++) {
        if (kt + 1 < KT) {
            int nkt = kt + 1;
            int k0 = (nkt & 31) * 16;
            if (nkt < 32) {
                av0 = *(const float4*)&g_xhat[(size_t)(bm + arow) * Hdim + k0 + ac4];
                av1 = *(const float4*)&g_xhat[(size_t)(bm + arow + 64) * Hdim + k0 + ac4];
                bv0 = *(const float4*)&Wx[(size_t)(k0 + brow) * H3 + bn + bc4];
                bv1 = *(const float4*)&Wx[(size_t)(k0 + brow + 8) * H3 + bn + bc4];
            } else {
                int4 m0 = *(const int4*)&mask[(size_t)(bm + arow) * Hdim + k0 + ac4];
                int4 m1 = *(const int4*)&mask[(size_t)(bm + arow + 64) * Hdim + k0 + ac4];
                av0 = make_float4((float)m0.x, (float)m0.y, (float)m0.z, (float)m0.w);
                av1 = make_float4((float)m1.x, (float)m1.y, (float)m1.z, (float)m1.w);
                bv0 = *(const float4*)&Wm[(size_t)(k0 + brow) * H3 + bn + bc4];
                bv1 = *(const float4*)&Wm[(size_t)(k0 + brow + 8) * H3 + bn + bc4];
            }
        }
        const unsigned* A = Afr[kt & 1];
        const unsigned* B = Bs[kt & 1];
        #pragma unroll
        for (int ks = 0; ks < 2; ks++) {
            unsigned af[4][4], bf[4][2];
            #pragma unroll
            for (int mt = 0; mt < 4; mt++) {
                uint4 fa = *(const uint4*)&A[(mbkw + mt) * AFRB + g * 36 + tg * 8 + ks * 4];
                af[mt][0] = fa.x; af[mt][1] = fa.y; af[mt][2] = fa.z; af[mt][3] = fa.w;
            }
            #pragma unroll
            for (int nt = 0; nt < 4; nt++) {
                int nb = wn + nt * 8;
                bf[nt][0] = B[(ks * 8 + tg) * BSTR + nb + g];
                bf[nt][1] = B[(ks * 8 + tg + 4) * BSTR + nb + g];
            }
            #pragma unroll
            for (int mt = 0; mt < 4; mt++)
                #pragma unroll
                for (int nt = 0; nt < 4; nt++)
                    mma_tf32(acc[mt][nt], af[mt], bf[nt]);
        }
        if (kt + 1 < KT) {
            unsigned* An = Afr[(kt + 1) & 1]; unsigned* Bn = Bs[(kt + 1) & 1];
            STORE_AFRAG(An, abase0, av0);
            STORE_AFRAG(An, abase1, av1);
            Bn[brow * BSTR + bc4 + 0] = f2tf32(bv0.x); Bn[brow * BSTR + bc4 + 1] = f2tf32(bv0.y);
            Bn[brow * BSTR + bc4 + 2] = f2tf32(bv0.z); Bn[brow * BSTR + bc4 + 3] = f2tf32(bv0.w);
            Bn[(brow + 8) * BSTR + bc4 + 0] = f2tf32(bv1.x); Bn[(brow + 8) * BSTR + bc4 + 1] = f2tf32(bv1.y);
            Bn[(brow + 8) * BSTR + bc4 + 2] = f2tf32(bv1.z); Bn[(brow + 8) * BSTR + bc4 + 3] = f2tf32(bv1.w);
        }
        __syncthreads();
    }

    #pragma unroll
    for (int mt = 0; mt < 4; mt++) {
        #pragma unroll
        for (int nt = 0; nt < 4; nt++) {
            int col = bn + wn + nt * 8 + tg * 2;
            float b0 = bias[col], b1 = bias[col + 1];
            int r0 = bm + wm + mt * 16 + g;
            float2 o0, o1;
            o0.x = acc[mt][nt][0] + b0; o0.y = acc[mt][nt][1] + b1;
            o1.x = acc[mt][nt][2] + b0; o1.y = acc[mt][nt][3] + b1;
            *(float2*)&g_pre[(size_t)r0 * H3 + col] = o0;
            *(float2*)&g_pre[(size_t)(r0 + 8) * H3 + col] = o1;
        }
    }
}

// ---------------- K6 (mma): out = h_seq @ W_out + b_out ----------------------
__global__ void __launch_bounds__(256, 2) k_out_mma(const float* __restrict__ Bw,
                                                    const float* __restrict__ bias,
                                                    float* __restrict__ out) {
    __shared__ __align__(16) unsigned Afr[2][AFRW];
    __shared__ unsigned Bs[2][16 * BSTR];
    const int tid = threadIdx.x;
    const int bn = blockIdx.x * 128, bm = blockIdx.y * 128;
    const int wid = tid >> 5, lane = tid & 31;
    const int wm = (wid >> 2) * 64, wn = (wid & 3) * 32;
    const int g = lane >> 2, tg = lane & 3;
    const int arow = tid >> 2, ac4 = (tid & 3) * 4;
    const int brow = tid >> 5, bc4 = lane * 4;
    const int abase0 = (arow >> 4) * AFRB + (arow & 7) * 36 + (ac4 >> 3) * 4
                     + ((arow >> 3) & 1) + ((ac4 >> 2) & 1) * 2;
    const int abase1 = abase0 + 4 * AFRB;
    const int mbkw = (wid >> 2) * 4;

    float acc[4][4][4];
    #pragma unroll
    for (int i = 0; i < 4; i++)
        #pragma unroll
        for (int j = 0; j < 4; j++)
            #pragma unroll
            for (int q = 0; q < 4; q++) acc[i][j][q] = 0.f;

    float4 av0, av1, bv0, bv1;
    av0 = *(const float4*)&g_hseq[(size_t)(bm + arow) * Hdim + ac4];
    av1 = *(const float4*)&g_hseq[(size_t)(bm + arow + 64) * Hdim + ac4];
    bv0 = *(const float4*)&Bw[(size_t)(brow) * OUTD + bn + bc4];
    bv1 = *(const float4*)&Bw[(size_t)(brow + 8) * OUTD + bn + bc4];
    {
        unsigned* A = Afr[0]; unsigned* B = Bs[0];
        STORE_AFRAG(A, abase0, av0);
        STORE_AFRAG(A, abase1, av1);
        B[brow * BSTR + bc4 + 0] = f2tf32(bv0.x); B[brow * BSTR + bc4 + 1] = f2tf32(bv0.y);
        B[brow * BSTR + bc4 + 2] = f2tf32(bv0.z); B[brow * BSTR + bc4 + 3] = f2tf32(bv0.w);
        B[(brow + 8) * BSTR + bc4 + 0] = f2tf32(bv1.x); B[(brow + 8) * BSTR + bc4 + 1] = f2tf32(bv1.y);
        B[(brow + 8) * BSTR + bc4 + 2] = f2tf32(bv1.z); B[(brow + 8) * BSTR + bc4 + 3] = f2tf32(bv1.w);
    }
    __syncthreads();

    const int KT = Hdim / 16;
    for (int kt = 0; kt < KT; kt++) {
        if (kt + 1 < KT) {
            int k0 = (kt + 1) * 16;
            av0 = *(const float4*)&g_hseq[(size_t)(bm + arow) * Hdim + k0 + ac4];
            av1 = *(const float4*)&g_hseq[(size_t)(bm + arow + 64) * Hdim + k0 + ac4];
            bv0 = *(const float4*)&Bw[(size_t)(k0 + brow) * OUTD + bn + bc4];
            bv1 = *(const float4*)&Bw[(size_t)(k0 + brow + 8) * OUTD + bn + bc4];
        }
        const unsigned* A = Afr[kt & 1];
        const unsigned* B = Bs[kt & 1];
        #pragma unroll
        for (int ks = 0; ks < 2; ks++) {
            unsigned af[4][4], bf[4][2];
            #pragma unroll
            for (int mt = 0; mt < 4; mt++) {
                uint4 fa = *(const uint4*)&A[(mbkw + mt) * AFRB + g * 36 + tg * 8 + ks * 4];
                af[mt][0] = fa.x; af[mt][1] = fa.y; af[mt][2] = fa.z; af[mt][3] = fa.w;
            }
            #pragma unroll
            for (int nt = 0; nt < 4; nt++) {
                int nb = wn + nt * 8;
                bf[nt][0] = B[(ks * 8 + tg) * BSTR + nb + g];
                bf[nt][1] = B[(ks * 8 + tg + 4) * BSTR + nb + g];
            }
            #pragma unroll
            for (int mt = 0; mt < 4; mt++)
                #pragma unroll
                for (int nt = 0; nt < 4; nt++)
                    mma_tf32(acc[mt][nt], af[mt], bf[nt]);
        }
        if (kt + 1 < KT) {
            unsigned* An = Afr[(kt + 1) & 1]; unsigned* Bn = Bs[(kt + 1) & 1];
            STORE_AFRAG(An, abase0, av0);
            STORE_AFRAG(An, abase1, av1);
            Bn[brow * BSTR + bc4 + 0] = f2tf32(bv0.x); Bn[brow * BSTR + bc4 + 1] = f2tf32(bv0.y);
            Bn[brow * BSTR + bc4 + 2] = f2tf32(bv0.z); Bn[brow * BSTR + bc4 + 3] = f2tf32(bv0.w);
            Bn[(brow + 8) * BSTR + bc4 + 0] = f2tf32(bv1.x); Bn[(brow + 8) * BSTR + bc4 + 1] = f2tf32(bv1.y);
            Bn[(brow + 8) * BSTR + bc4 + 2] = f2tf32(bv1.z); Bn[(brow + 8) * BSTR + bc4 + 3] = f2tf32(bv1.w);
        }
        __syncthreads();
    }

    #pragma unroll
    for (int mt = 0; mt < 4; mt++) {
        #pragma unroll
        for (int nt = 0; nt < 4; nt++) {
            int col = bn + wn + nt * 8 + tg * 2;
            float b0 = bias[col], b1 = bias[col + 1];
            int r0 = bm + wm + mt * 16 + g;
            float2 o0, o1;
            o0.x = acc[mt][nt][0] + b0; o0.y = acc[mt][nt][1] + b1;
            o1.x = acc[mt][nt][2] + b0; o1.y = acc[mt][nt][3] + b1;
            *(float2*)&out[(size_t)r0 * OUTD + col] = o0;
            *(float2*)&out[(size_t)(r0 + 8) * OUTD + col] = o1;
        }
    }
}

// =============================================================================
// K5: persistent sequential recurrence — fp16 data plane + m16n8k16 fp16 MMA.
// Structure/barriers/prefetches identical to R9. Smem in half2 words.
// =============================================================================
#define OFF_WH1 0                 // [256 kpairs][40] half2 words
#define WS1H    40
#define OFF_WH3 10240             // [256][24]
#define WS3H    24
#define OFF_AB  16384             // [32 rows][260] half2 words (256 + 4 pad)
#define ASH     260
#define OFF_RED 24704             // float [8][32][36] / [8][32][20]
#define RSTR1   36
#define RKG1    (32*RSTR1)
#define RSTR2   20
#define RKG2    (32*RSTR2)
#define SMEM_SEQ ((OFF_RED + 8*RKG1) * 4)   // 135680 B

__global__ void __launch_bounds__(256, 1) k_seq(const float* __restrict__ Wh) {
    extern __shared__ unsigned smu[];
    unsigned* Wh1h = smu + OFF_WH1;
    unsigned* Wh3h = smu + OFF_WH3;
    unsigned* Abh  = smu + OFF_AB;
    float*    Red  = (float*)(smu + OFF_RED);

    const int tid = threadIdx.x;
    const int blk = blockIdx.x;
    const int rg  = blk >> 5;
    const int tn  = blk & 31;
    const int m0  = rg * 32;
    const int n0  = tn * 32;
    const int n02 = tn * 16;

    // convert Wh panels to fp16 (half2 along K) once
    for (int i = tid; i < 256 * 32; i += 256) {
        int kp = i >> 5, n = i & 31;
        float lo = Wh[(size_t)(2 * kp) * H3 + n0 + n];
        float hi = Wh[(size_t)(2 * kp + 1) * H3 + n0 + n];
        Wh1h[kp * WS1H + n] = pack_h2(lo, hi);
    }
    for (int i = tid; i < 256 * 16; i += 256) {
        int kp = i >> 4, n = i & 15;
        float lo = Wh[(size_t)(2 * kp) * H3 + 1024 + n02 + n];
        float hi = Wh[(size_t)(2 * kp + 1) * H3 + 1024 + n02 + n];
        Wh3h[kp * WS3H + n] = pack_h2(lo, hi);
    }
    if (tn == 0)
        for (int i = tid; i < 32 * 512; i += 256) g_h[m0 * 512 + i] = 0.f;
    groupbar(rg);

    const int lane = tid & 31, kg = tid >> 5;
    const int g = lane >> 2, tg = lane & 3;
    const int kpbase = (kg * 64) >> 1;            // warp K-slice in kpairs
    const int pr = tid >> 3, pc = (tid & 7) * 4;  // produce1 mapping
    const int pw = (tid & 7) * 4;                 // produce2 word base
    const int rr1 = tid >> 3, cc1 = (tid * 4) & 31;
    const int rr2 = tid >> 3, cc2 = (tid * 2) & 15;
    const int nn1 = (n0 >= 512 ? n0 - 512 : 0) + cc1;

    for (int step = 0; step < Ldim; step++) {
        // ---------- epilogue prefetches (overlap with produce+GEMM1) ----------
        float4 pf_pre4 = __ldcg((const float4*)&g_pre[(size_t)((m0 + rr1) * Ldim + step) * H3 + n0 + cc1]);
        float2 pf_pre2 = __ldcg((const float2*)&g_pre[(size_t)((m0 + rr2) * Ldim + step) * H3 + 1024 + n02 + cc2]);
        unsigned pf_gm2u = *(const unsigned*)&g_gammah[(size_t)((m0 + rr2) * Ldim + step) * 512 + n02 + cc2];
        float2 pf_h2   = __ldcg((const float2*)&g_h[(m0 + rr2) * 512 + n02 + cc2]);
        uint2  pf_gm1u = *(const uint2*)&g_gammah[(size_t)((m0 + rr1) * Ldim + step) * 512 + nn1];
        float4 pf_h1   = __ldcg((const float4*)&g_h[(m0 + rr1) * 512 + nn1]);

        // ---------- produce A = gamma(step) ⊙ h -> half2 ----------
        {
            const float* hrow = g_h + (m0 + pr) * 512;
            const __half* grow = g_gammah + (size_t)((m0 + pr) * Ldim + step) * 512;
            #pragma unroll
            for (int j = 0; j < 16; j++) {
                int k = pc + 32 * j;
                float4 h4 = __ldcg((const float4*)(hrow + k));
                uint2 gp = *(const uint2*)(grow + k);
                float2 f01 = h2f2(gp.x), f23 = h2f2(gp.y);
                unsigned o0 = pack_h2(h4.x * f01.x, h4.y * f01.y);
                unsigned o1 = pack_h2(h4.z * f23.x, h4.w * f23.y);
                *(uint2*)&Abh[pr * ASH + (k >> 1)] = make_uint2(o0, o1);
            }
        }
        __syncthreads();
        // ---------- GEMM1 (fp16 mma m16n8k16): 32x32, K-slice 64 per warp -----
        {
            float acc[2][4][4];
            #pragma unroll
            for (int mt = 0; mt < 2; mt++)
                #pragma unroll
                for (int nt = 0; nt < 4; nt++)
                    #pragma unroll
                    for (int q = 0; q < 4; q++) acc[mt][nt][q] = 0.f;
            #pragma unroll
            for (int ks = 0; ks < 4; ks++) {
                int kp0 = kpbase + ks * 8;
                unsigned af[2][4];
                #pragma unroll
                for (int mt = 0; mt < 2; mt++) {
                    int mb = mt * 16;
                    af[mt][0] = Abh[(mb + g) * ASH + kp0 + tg];
                    af[mt][1] = Abh[(mb + g + 8) * ASH + kp0 + tg];
                    af[mt][2] = Abh[(mb + g) * ASH + kp0 + tg + 4];
                    af[mt][3] = Abh[(mb + g + 8) * ASH + kp0 + tg + 4];
                }
                unsigned bf[4][2];
                #pragma unroll
                for (int nt = 0; nt < 4; nt++) {
                    bf[nt][0] = Wh1h[(kp0 + tg) * WS1H + nt * 8 + g];
                    bf[nt][1] = Wh1h[(kp0 + tg + 4) * WS1H + nt * 8 + g];
                }
                #pragma unroll
                for (int mt = 0; mt < 2; mt++)
                    #pragma unroll
                    for (int nt = 0; nt < 4; nt++)
                        mma_f16(acc[mt][nt], af[mt], bf[nt]);
            }
            #pragma unroll
            for (int mt = 0; mt < 2; mt++)
                #pragma unroll
                for (int nt = 0; nt < 4; nt++) {
                    float* base = &Red[kg * RKG1 + (mt * 16 + g) * RSTR1 + nt * 8 + tg * 2];
                    *(float2*)base = make_float2(acc[mt][nt][0], acc[mt][nt][1]);
                    *(float2*)(base + 8 * RSTR1) = make_float2(acc[mt][nt][2], acc[mt][nt][3]);
                }
        }
        __syncthreads();
        // ---------- red1: reduce + sigmoid; z or rh(fp16) ----------
        {
            float4 s = *(float4*)&Red[rr1 * RSTR1 + cc1];
            #pragma unroll
            for (int q = 1; q < 8; q++) {
                float4 v = *(float4*)&Red[q * RKG1 + rr1 * RSTR1 + cc1];
                s.x += v.x; s.y += v.y; s.z += v.z; s.w += v.w;
            }
            int b = m0 + rr1;
            float s0 = sigmoidf_(s.x + pf_pre4.x);
            float s1 = sigmoidf_(s.y + pf_pre4.y);
            float s2 = sigmoidf_(s.z + pf_pre4.z);
            float s3 = sigmoidf_(s.w + pf_pre4.w);
            if (n0 < 512) {
                *(float4*)&g_z[b * 512 + n0 + cc1] = make_float4(s0, s1, s2, s3);
            } else {
                float2 ga = h2f2(pf_gm1u.x), gb = h2f2(pf_gm1u.y);
                unsigned r01 = pack_h2(s0 * ga.x * pf_h1.x, s1 * ga.y * pf_h1.y);
                unsigned r23 = pack_h2(s2 * gb.x * pf_h1.z, s3 * gb.y * pf_h1.w);
                *(uint2*)&g_rh[b * 512 + nn1] = make_uint2(r01, r23);
            }
        }
        groupbar(rg);

        // ---------- post-barrier prefetch: z ----------
        float2 pf_z2 = __ldcg((const float2*)&g_z[(m0 + rr2) * 512 + n02 + cc2]);

        // ---------- produce A = rh (fp16, pure copy) ----------
        {
            const unsigned* rrow = (const unsigned*)(g_rh + (m0 + pr) * 512);
            #pragma unroll
            for (int j = 0; j < 8; j++) {
                int w = pw + 32 * j;
                *(uint4*)&Abh[pr * ASH + w] = __ldcg((const uint4*)(rrow + w));
            }
        }
        __syncthreads();
        // ---------- GEMM2 (fp16 mma): 32x16, K-slice 64 per warp ----------
        {
            float acc[2][2][4];
            #pragma unroll
            for (int mt = 0; mt < 2; mt++)
                #pragma unroll
                for (int nt = 0; nt < 2; nt++)
                    #pragma unroll
                    for (int q = 0; q < 4; q++) acc[mt][nt][q] = 0.f;
            #pragma unroll
            for (int ks = 0; ks < 4; ks++) {
                int kp0 = kpbase + ks * 8;
                unsigned af[2][4];
                #pragma unroll
                for (int mt = 0; mt < 2; mt++) {
                    int mb = mt * 16;
                    af[mt][0] = Abh[(mb + g) * ASH + kp0 + tg];
                    af[mt][1] = Abh[(mb + g + 8) * ASH + kp0 + tg];
                    af[mt][2] = Abh[(mb + g) * ASH + kp0 + tg + 4];
                    af[mt][3] = Abh[(mb + g + 8) * ASH + kp0 + tg + 4];
                }
                unsigned bf[2][2];
                #pragma unroll
                for (int nt = 0; nt < 2; nt++) {
                    bf[nt][0] = Wh3h[(kp0 + tg) * WS3H + nt * 8 + g];
                    bf[nt][1] = Wh3h[(kp0 + tg + 4) * WS3H + nt * 8 + g];
                }
                #pragma unroll
                for (int mt = 0; mt < 2; mt++)
                    #pragma unroll
                    for (int nt = 0; nt < 2; nt++)
                        mma_f16(acc[mt][nt], af[mt], bf[nt]);
            }
            #pragma unroll
            for (int mt = 0; mt < 2; mt++)
                #pragma unroll
                for (int nt = 0; nt < 2; nt++) {
                    float* base = &Red[kg * RKG2 + (mt * 16 + g) * RSTR2 + nt * 8 + tg * 2];
                    *(float2*)base = make_float2(acc[mt][nt][0], acc[mt][nt][1]);
                    *(float2*)(base + 8 * RSTR2) = make_float2(acc[mt][nt][2], acc[mt][nt][3]);
                }
        }
        __syncthreads();
        // ---------- red2: reduce + gates + h update ----------
        {
            float2 s = *(float2*)&Red[rr2 * RSTR2 + cc2];
            #pragma unroll
            for (int q = 1; q < 8; q++) {
                float2 v = *(float2*)&Red[q * RKG2 + rr2 * RSTR2 + cc2];
                s.x += v.x; s.y += v.y;
            }
            int b = m0 + rr2, n = n02 + cc2;
            float2 gm = h2f2(pf_gm2u);
            float ht0 = tanhf(s.x + pf_pre2.x), ht1 = tanhf(s.y + pf_pre2.y);
            float hd0 = gm.x * pf_h2.x, hd1 = gm.y * pf_h2.y;
            float hn0 = (1.f - pf_z2.x) * hd0 + pf_z2.x * ht0;
            float hn1 = (1.f - pf_z2.y) * hd1 + pf_z2.y * ht1;
            *(float2*)&g_h[b * 512 + n] = make_float2(hn0, hn1);
            *(float2*)&g_hseq[(size_t)(b * Ldim + step) * 512 + n] = make_float2(hn0, hn1);
        }
        groupbar(rg);
    }
}

// ---------------- launch -----------------------------------------------------
extern "C" void kernel_launch(void* const* d_in, const int* in_sizes, int n_in,
                              void* d_out, int out_size) {
    const float* C     = (const float*)d_in[0];
    const float* t     = (const float*)d_in[1];
    const int*   mask  = (const int*)  d_in[2];
    const float* Wx    = (const float*)d_in[3];
    const float* Wh    = (const float*)d_in[4];
    const float* Wm    = (const float*)d_in[5];
    const float* bvec  = (const float*)d_in[6];
    const float* w_gx  = (const float*)d_in[7];
    const float* b_gx  = (const float*)d_in[8];
    const float* W_gh  = (const float*)d_in[9];
    const float* b_gh  = (const float*)d_in[10];
    const float* W_out = (const float*)d_in[11];
    const float* b_out = (const float*)d_in[12];
    float* out = (float*)d_out;

    cudaFuncSetAttribute(k_seq, cudaFuncAttributeMaxDynamicSharedMemorySize, SMEM_SEQ);

    k_xmean<<<Bdim * Hdim / 256, 256>>>(C, mask);
    k_scan <<<Bdim * Hdim / 256, 256>>>(C, t, mask, w_gx, b_gx);
    k_gh_mma <<<dim3(Hdim / 128, BL / 128), 256>>>(W_gh, b_gh);
    k_pre_mma<<<dim3(H3 / 128,  BL / 128), 256>>>(mask, Wx, Wm, bvec);
    k_seq<<<NBLK, 256, SMEM_SEQ>>>(Wh);
    k_out_mma<<<dim3(OUTD / 128, BL / 128), 256>>>(W_out, b_out, out);
}